// round 7
// baseline (speedup 1.0000x reference)
#include <cuda_runtime.h>
#include <math.h>

#define NT 256
typedef unsigned long long u64;

// f32x2 packed math (Blackwell): two fp32 FMAs per instruction
#define FMA2(d,a,b)  asm("fma.rn.f32x2 %0, %1, %2, %0;" : "+l"(d) : "l"(a), "l"(b))
#define UNPK(lo,hi,p) asm("mov.b64 {%0,%1}, %2;" : "=f"(lo), "=f"(hi) : "l"(p))
#define PK(p,lo,hi)   asm("mov.b64 %0, {%1,%2};" : "=l"(p) : "f"(lo), "f"(hi))

// ---------------- device scratch ----------------
__device__ __align__(16) float g_geo[4096];
__device__ __align__(16) float g_p16[4096];   // pattern part of pm1 + pm1_b per (n,j)
__device__ __align__(16) float g_wq[4096];
__device__ __align__(16) float g_wk[4096];
__device__ __align__(16) float g_wv[4096];
__device__ __align__(16) float g_bq[64];
__device__ __align__(16) float g_bk[64];
__device__ __align__(16) float g_bv[64];

// ---------------- prep: geo, P16, fused QKV weights ----------------
__global__ void esa_prep_kernel(const float* __restrict__ points,
                                const int*   __restrict__ adjacency,
                                const float* __restrict__ in_w,
                                const float* __restrict__ in_b,
                                const float* __restrict__ pattern,
                                const float* __restrict__ pm1_w,
                                const float* __restrict__ pm1_b,
                                const float* __restrict__ q_w, const float* __restrict__ q_b,
                                const float* __restrict__ k_w, const float* __restrict__ k_b,
                                const float* __restrict__ v_w, const float* __restrict__ v_b)
{
    const int gtid = blockIdx.x * blockDim.x + threadIdx.x;
    const int gstride = gridDim.x * blockDim.x;
    const float scale = 0.3535533905932738f; // 1/sqrt(8)

    for (int idx = gtid; idx < 4096; idx += gstride) {
        int n = idx >> 6, m = idx & 63;
        float dx = points[n*3+0] - points[m*3+0];
        float dy = points[n*3+1] - points[m*3+1];
        float dz = points[n*3+2] - points[m*3+2];
        float dist = sqrtf(dx*dx + dy*dy + dz*dz + 1e-12f);
        g_geo[idx] = (adjacency[idx] > 0) ? 0.5f : (-0.1f / (1.0f + dist));
    }
    for (int idx = gtid; idx < 4096; idx += gstride) {
        int n = idx >> 6, j = idx & 63;
        float s = pm1_b[j];
        const float* wr = pm1_w + j*80 + 64;
        const float* pr = pattern + n*16;
        #pragma unroll
        for (int p = 0; p < 16; p++) s += pr[p] * wr[p];
        g_p16[idx] = s;
    }
    for (int idx = gtid; idx < 3*4096; idx += gstride) {
        int which = idx >> 12;
        int o = (idx >> 6) & 63;
        int u = idx & 63;
        const float* wi = in_w + which*4096 + o*64;
        const float* wx = (which==0) ? q_w : (which==1) ? k_w : v_w;
        float s = 0.f;
        #pragma unroll 4
        for (int t = 0; t < 64; t++) s += wi[t] * wx[t*64 + u];
        if (which == 0) s *= scale;
        float* dst = (which==0) ? g_wq : (which==1) ? g_wk : g_wv;
        dst[o*64 + u] = s;
    }
    for (int idx = gtid; idx < 192; idx += gstride) {
        int which = idx >> 6, o = idx & 63;
        const float* wi = in_w + which*4096 + o*64;
        const float* bx = (which==0) ? q_b : (which==1) ? k_b : v_b;
        float s = in_b[which*64 + o];
        for (int t = 0; t < 64; t++) s += wi[t] * bx[t];
        if (which == 0) s *= scale;
        float* dst = (which==0) ? g_bq : (which==1) ? g_bk : g_bv;
        dst[o] = s;
    }
}

// ---------------- weight staging (all 256 threads, 4 float4 each) ----------------
__device__ __forceinline__ void pre_ld(const float* __restrict__ src, int sstr,
                                       float4* r, int tid) {
    #pragma unroll
    for (int i = 0; i < 4; i++) {
        int idx4 = tid + i*NT;
        int rr = idx4 >> 4, cc = (idx4 & 15) << 2;
        r[i] = __ldg((const float4*)(src + rr*sstr + cc));
    }
}
__device__ __forceinline__ void pre_st(float* __restrict__ Wd, const float4* r, int tid) {
    #pragma unroll
    for (int i = 0; i < 4; i++) {
        int idx4 = tid + i*NT;
        int rr = idx4 >> 4, cc = (idx4 & 15) << 2;
        *(float4*)(Wd + rr*68 + cc) = r[i];
    }
}

// ---------------- 2-element f32x2 GEMM: b registers shared across elements ----------
// per element: rows n0..n0+3 (n0=(tid>>4)*4), cols j0+16j (j0=tid&15)
template<bool RELU, bool BIASMAT>
__device__ __forceinline__ void gemm2e(const float* __restrict__ in0,
                                       const float* __restrict__ in1, int sin,
                                       const float* __restrict__ W,
                                       const float* __restrict__ bias,
                                       float* __restrict__ out0,
                                       float* __restrict__ out1, int so, int tid)
{
    const int n0 = (tid >> 4) << 2;
    const int j0 = tid & 15;
    u64 ac0[4][4], ac1[4][4];
    #pragma unroll
    for (int i = 0; i < 4; i++)
        #pragma unroll
        for (int j = 0; j < 4; j++) { ac0[i][j] = 0ull; ac1[i][j] = 0ull; }

    const float* ap0 = in0 + n0*sin;
    const float* ap1 = in1 + n0*sin;
    const float* wp  = W + j0*68;
    #pragma unroll 4
    for (int k = 0; k < 64; k += 4) {
        ulonglong2 b[4];
        b[0] = *(const ulonglong2*)(wp + k);
        b[1] = *(const ulonglong2*)(wp + 16*68 + k);
        b[2] = *(const ulonglong2*)(wp + 32*68 + k);
        b[3] = *(const ulonglong2*)(wp + 48*68 + k);
        #pragma unroll
        for (int i = 0; i < 4; i++) {
            ulonglong2 a0 = *(const ulonglong2*)(ap0 + i*sin + k);
            ulonglong2 a1 = *(const ulonglong2*)(ap1 + i*sin + k);
            #pragma unroll
            for (int j = 0; j < 4; j++) {
                FMA2(ac0[i][j], a0.x, b[j].x);
                FMA2(ac0[i][j], a0.y, b[j].y);
                FMA2(ac1[i][j], a1.x, b[j].x);
                FMA2(ac1[i][j], a1.y, b[j].y);
            }
        }
    }
    #pragma unroll
    for (int j = 0; j < 4; j++) {
        int jj = j0 + 16*j;
        float bj = BIASMAT ? 0.f : __ldg(bias + jj);
        #pragma unroll
        for (int i = 0; i < 4; i++) {
            int row = n0 + i;
            float bm = BIASMAT ? __ldg(bias + row*64 + jj) : bj;
            float lo, hi;
            UNPK(lo, hi, ac0[i][j]);
            float v0 = lo + hi + bm;
            UNPK(lo, hi, ac1[i][j]);
            float v1 = lo + hi + bm;
            if (RELU) { v0 = fmaxf(v0, 0.f); v1 = fmaxf(v1, 0.f); }
            out0[row*so + jj] = v0;
            out1[row*so + jj] = v1;
        }
    }
}

// mo projection: fused +geo +residual epilogue, 2 elements
__device__ __forceinline__ void gemm_mo2e(const float* __restrict__ in0,
                                          const float* __restrict__ in1,
                                          const float* __restrict__ W,
                                          const float* __restrict__ mo_b,
                                          const float* __restrict__ pf0,
                                          const float* __restrict__ pf1,
                                          float* __restrict__ out0,
                                          float* __restrict__ out1, int tid)
{
    const int n0 = (tid >> 4) << 2;
    const int j0 = tid & 15;
    u64 ac0[4][4], ac1[4][4];
    #pragma unroll
    for (int i = 0; i < 4; i++)
        #pragma unroll
        for (int j = 0; j < 4; j++) { ac0[i][j] = 0ull; ac1[i][j] = 0ull; }

    const float* ap0 = in0 + n0*68;
    const float* ap1 = in1 + n0*68;
    const float* wp  = W + j0*68;
    #pragma unroll 4
    for (int k = 0; k < 64; k += 4) {
        ulonglong2 b[4];
        b[0] = *(const ulonglong2*)(wp + k);
        b[1] = *(const ulonglong2*)(wp + 16*68 + k);
        b[2] = *(const ulonglong2*)(wp + 32*68 + k);
        b[3] = *(const ulonglong2*)(wp + 48*68 + k);
        #pragma unroll
        for (int i = 0; i < 4; i++) {
            ulonglong2 a0 = *(const ulonglong2*)(ap0 + i*68 + k);
            ulonglong2 a1 = *(const ulonglong2*)(ap1 + i*68 + k);
            #pragma unroll
            for (int j = 0; j < 4; j++) {
                FMA2(ac0[i][j], a0.x, b[j].x);
                FMA2(ac0[i][j], a0.y, b[j].y);
                FMA2(ac1[i][j], a1.x, b[j].x);
                FMA2(ac1[i][j], a1.y, b[j].y);
            }
        }
    }
    #pragma unroll
    for (int j = 0; j < 4; j++) {
        int jj = j0 + 16*j;
        float bj = __ldg(mo_b + jj);
        #pragma unroll
        for (int i = 0; i < 4; i++) {
            int row = n0 + i;
            float gg = __ldg(g_geo + row*64 + jj) + bj;
            float lo, hi;
            UNPK(lo, hi, ac0[i][j]);
            out0[row*68 + jj] = lo + hi + gg + pf0[row*68 + jj];
            UNPK(lo, hi, ac1[i][j]);
            out1[row*68 + jj] = lo + hi + gg + pf1[row*68 + jj];
        }
    }
}

// final projection: straight to global, transposed layout (out[c][n]), 2 elements
__device__ __forceinline__ void gemm_out2e(const float* __restrict__ in0,
                                           const float* __restrict__ in1,
                                           const float* __restrict__ W,
                                           const float* __restrict__ bias,
                                           float* __restrict__ og0,
                                           float* __restrict__ og1, int tid)
{
    const int n0 = (tid >> 4) << 2;
    const int j0 = tid & 15;
    u64 ac0[4][4], ac1[4][4];
    #pragma unroll
    for (int i = 0; i < 4; i++)
        #pragma unroll
        for (int j = 0; j < 4; j++) { ac0[i][j] = 0ull; ac1[i][j] = 0ull; }

    const float* ap0 = in0 + n0*68;
    const float* ap1 = in1 + n0*68;
    const float* wp  = W + j0*68;
    #pragma unroll 4
    for (int k = 0; k < 64; k += 4) {
        ulonglong2 b[4];
        b[0] = *(const ulonglong2*)(wp + k);
        b[1] = *(const ulonglong2*)(wp + 16*68 + k);
        b[2] = *(const ulonglong2*)(wp + 32*68 + k);
        b[3] = *(const ulonglong2*)(wp + 48*68 + k);
        #pragma unroll
        for (int i = 0; i < 4; i++) {
            ulonglong2 a0 = *(const ulonglong2*)(ap0 + i*68 + k);
            ulonglong2 a1 = *(const ulonglong2*)(ap1 + i*68 + k);
            #pragma unroll
            for (int j = 0; j < 4; j++) {
                FMA2(ac0[i][j], a0.x, b[j].x);
                FMA2(ac0[i][j], a0.y, b[j].y);
                FMA2(ac1[i][j], a1.x, b[j].x);
                FMA2(ac1[i][j], a1.y, b[j].y);
            }
        }
    }
    #pragma unroll
    for (int j = 0; j < 4; j++) {
        int jj = j0 + 16*j;
        float bj = __ldg(bias + jj);
        #pragma unroll
        for (int i = 0; i < 4; i++) {
            int row = n0 + i;
            float lo, hi;
            UNPK(lo, hi, ac0[i][j]);
            og0[jj*64 + row] = lo + hi + bj;
            UNPK(lo, hi, ac1[i][j]);
            og1[jj*64 + row] = lo + hi + bj;
        }
    }
}

// conv tap: 4 outputs with shifted 3-tap window, accs named
#define CONVTAP(XP, CC, W0m, W1m, W2m, q0, q1, q2, q3) { \
    const float* xr = (XP) + (CC)*68 + base; \
    float4 xv = *(const float4*)xr; float2 xt = *(const float2*)(xr+4); \
    q0 += (W0m)*xv.x + (W1m)*xv.y + (W2m)*xv.z; \
    q1 += (W0m)*xv.y + (W1m)*xv.z + (W2m)*xv.w; \
    q2 += (W0m)*xv.z + (W1m)*xv.w + (W2m)*xt.x; \
    q3 += (W0m)*xv.w + (W1m)*xt.x + (W2m)*xt.y; }

// gemm phase: all threads compute, weights for NEXT phase prefetched around it
#define GPHASE(RELU, BM, IN0, IN1, SIN, WCUR, BIAS, OUT0, OUT1, SO, NXT, NSTR, WNXT) { \
    float4 pf4[4]; pre_ld(NXT, NSTR, pf4, tid); \
    gemm2e<RELU, BM>(IN0, IN1, SIN, WCUR, BIAS, OUT0, OUT1, SO, tid); \
    pre_st(WNXT, pf4, tid); \
    __syncthreads(); }

// ---------------- main kernel: one CTA per 2 batch elements ----------------
// smem (floats): W0 0(4352) | W1 4352(4352) | then per element e (base 8704+e*18496):
//   X +0(4352) | Y1 +4352(1088) | CB +5440(4352) | T +9792(4352) | PF +14144(4352)
#define SMEM_FLOATS 45696

__global__ void __launch_bounds__(NT, 1)
esa_main_kernel(const float* __restrict__ x,
                const float* __restrict__ conv1_w, const float* __restrict__ conv1_b,
                const float* __restrict__ conv2_w, const float* __restrict__ conv2_b,
                const float* __restrict__ pm1_w,
                const float* __restrict__ pm2_w, const float* __restrict__ pm2_b,
                const float* __restrict__ mo_w,  const float* __restrict__ mo_b,
                const float* __restrict__ out_w, const float* __restrict__ out_b,
                const float* __restrict__ ln_g,  const float* __restrict__ ln_b,
                float* __restrict__ out)
{
    extern __shared__ float sm[];
    const int tid = threadIdx.x;
    const int b = blockIdx.x;
    float* W0 = sm;
    float* W1 = sm + 4352;
    float* X0  = sm + 8704;              float* X1  = X0 + 18496;
    float* Y10 = X0 + 4352;              float* Y11 = Y10 + 18496;
    float* CB0 = X0 + 5440;              float* CB1 = CB0 + 18496;
    float* T0  = X0 + 9792;              float* T1  = T0 + 18496;
    float* PF0 = X0 + 14144;             float* PF1 = PF0 + 18496;

    // ---- load x for both elements + stage pm1 (cols 0..63) into W0 ----
    {
        float4 pw[4]; pre_ld(pm1_w, 80, pw, tid);
        const float* xg = x + (size_t)(2*b) * 4096;
        for (int idx4 = tid; idx4 < 2048; idx4 += NT) {
            float4 v = __ldg((const float4*)xg + idx4);
            int e = idx4 >> 10, i = idx4 & 1023;
            int c = i >> 4, n = (i & 15) << 2;
            float* rr = (e ? X1 : X0) + c*68 + 1 + n;
            rr[0] = v.x; rr[1] = v.y; rr[2] = v.z; rr[3] = v.w;
        }
        pre_st(W0, pw, tid);
        if (tid < 64) {
            X0[tid*68] = 0.f; X0[tid*68 + 65] = 0.f;
            X1[tid*68] = 0.f; X1[tid*68 + 65] = 0.f;
        }
        if (tid < 16) {
            Y10[tid*68] = 0.f; Y10[tid*68 + 65] = 0.f;
            Y11[tid*68] = 0.f; Y11[tid*68 + 65] = 0.f;
        }
    }
    __syncthreads();

    // ---- 4-scale conv stack, both elements share weight registers ----
    for (int s = 0; s < 4; s++) {
        {
            int o = tid >> 4, nq = tid & 15, base = nq*4;
            const float* wr = conv1_w + s*3072 + o*192;
            float a0=0.f,a1=0.f,a2=0.f,a3=0.f, c0=0.f,c1=0.f,c2=0.f,c3=0.f;
            #pragma unroll 4
            for (int c = 0; c < 64; c += 4) {
                float4 wA = __ldg((const float4*)(wr + c*3));
                float4 wB = __ldg((const float4*)(wr + c*3 + 4));
                float4 wC = __ldg((const float4*)(wr + c*3 + 8));
                CONVTAP(X0, c+0, wA.x, wA.y, wA.z, a0,a1,a2,a3);
                CONVTAP(X0, c+1, wA.w, wB.x, wB.y, a0,a1,a2,a3);
                CONVTAP(X0, c+2, wB.z, wB.w, wC.x, a0,a1,a2,a3);
                CONVTAP(X0, c+3, wC.y, wC.z, wC.w, a0,a1,a2,a3);
                CONVTAP(X1, c+0, wA.x, wA.y, wA.z, c0,c1,c2,c3);
                CONVTAP(X1, c+1, wA.w, wB.x, wB.y, c0,c1,c2,c3);
                CONVTAP(X1, c+2, wB.z, wB.w, wC.x, c0,c1,c2,c3);
                CONVTAP(X1, c+3, wC.y, wC.z, wC.w, c0,c1,c2,c3);
            }
            float bb = __ldg(conv1_b + s*16 + o);
            float* yr0 = Y10 + o*68 + 1 + base;
            float* yr1 = Y11 + o*68 + 1 + base;
            yr0[0]=fmaxf(a0+bb,0.f); yr0[1]=fmaxf(a1+bb,0.f); yr0[2]=fmaxf(a2+bb,0.f); yr0[3]=fmaxf(a3+bb,0.f);
            yr1[0]=fmaxf(c0+bb,0.f); yr1[1]=fmaxf(c1+bb,0.f); yr1[2]=fmaxf(c2+bb,0.f); yr1[3]=fmaxf(c3+bb,0.f);
        }
        __syncthreads();
        {
            int o = tid >> 4, nq = tid & 15, base = nq*4;
            const float* wr = conv2_w + s*768 + o*48;
            float a0=0.f,a1=0.f,a2=0.f,a3=0.f, c0=0.f,c1=0.f,c2=0.f,c3=0.f;
            #pragma unroll
            for (int c = 0; c < 16; c += 4) {
                float4 wA = __ldg((const float4*)(wr + c*3));
                float4 wB = __ldg((const float4*)(wr + c*3 + 4));
                float4 wC = __ldg((const float4*)(wr + c*3 + 8));
                CONVTAP(Y10, c+0, wA.x, wA.y, wA.z, a0,a1,a2,a3);
                CONVTAP(Y10, c+1, wA.w, wB.x, wB.y, a0,a1,a2,a3);
                CONVTAP(Y10, c+2, wB.z, wB.w, wC.x, a0,a1,a2,a3);
                CONVTAP(Y10, c+3, wC.y, wC.z, wC.w, a0,a1,a2,a3);
                CONVTAP(Y11, c+0, wA.x, wA.y, wA.z, c0,c1,c2,c3);
                CONVTAP(Y11, c+1, wA.w, wB.x, wB.y, c0,c1,c2,c3);
                CONVTAP(Y11, c+2, wB.z, wB.w, wC.x, c0,c1,c2,c3);
                CONVTAP(Y11, c+3, wC.y, wC.z, wC.w, c0,c1,c2,c3);
            }
            float bb = __ldg(conv2_b + s*16 + o);
            int ch = s*16 + o;
            CB0[(base+0)*68+ch]=fmaxf(a0+bb,0.f); CB0[(base+1)*68+ch]=fmaxf(a1+bb,0.f);
            CB0[(base+2)*68+ch]=fmaxf(a2+bb,0.f); CB0[(base+3)*68+ch]=fmaxf(a3+bb,0.f);
            CB1[(base+0)*68+ch]=fmaxf(c0+bb,0.f); CB1[(base+1)*68+ch]=fmaxf(c1+bb,0.f);
            CB1[(base+2)*68+ch]=fmaxf(c2+bb,0.f); CB1[(base+3)*68+ch]=fmaxf(c3+bb,0.f);
        }
        __syncthreads();
    }

    // ---- GEMM chain, weights double-buffered, b regs shared across elements ----
    GPHASE(true,  true,  CB0, CB1, 68, W0, g_p16, T0,  T1,  68, pm2_w, 64, W1);  // pm1
    GPHASE(false, false, T0,  T1,  68, W1, pm2_b, PF0, PF1, 68, g_wq,  64, W0);  // pm2
    GPHASE(false, false, PF0, PF1, 68, W0, g_bq,  CB0, CB1, 68, g_wk,  64, W1);  // Q
    GPHASE(false, false, PF0, PF1, 68, W1, g_bk,  T0,  T1,  68, g_wv,  64, W0);  // K
    GPHASE(false, false, PF0, PF1, 68, W0, g_bv,  X0,  X1,  68, mo_w,  64, W1);  // V

    // ---- attention: both elements sequentially; thread = (n, head-block) ----
    #pragma unroll
    for (int e = 0; e < 2; e++) {
        float* CB = e ? CB1 : CB0;
        float* T  = e ? T1  : T0;
        float* X  = e ? X1  : X0;
        const int n  = tid & 63;
        const int hb = tid >> 6;
        #pragma unroll
        for (int it = 0; it < 2; it++) {
            const int h8 = (hb + 4*it) * 8;
            float* qr = CB + n*68 + h8;
            ulonglong2 qa = *(const ulonglong2*)qr;
            ulonglong2 qb = *(const ulonglong2*)(qr + 4);
            float sc[64];
            float mx = -3.0e38f;
            #pragma unroll
            for (int m = 0; m < 64; m++) {
                const float* kr = T + m*68 + h8;
                ulonglong2 ka = *(const ulonglong2*)kr;
                ulonglong2 kb = *(const ulonglong2*)(kr + 4);
                u64 d = 0ull;
                FMA2(d, qa.x, ka.x); FMA2(d, qa.y, ka.y);
                FMA2(d, qb.x, kb.x); FMA2(d, qb.y, kb.y);
                float lo, hi; UNPK(lo, hi, d);
                float sv = lo + hi;
                sc[m] = sv; mx = fmaxf(mx, sv);
            }
            u64 c01 = 0ull, c23 = 0ull, c45 = 0ull, c67 = 0ull;
            float sum = 0.f;
            #pragma unroll
            for (int m = 0; m < 64; m++) {
                float ev = __expf(sc[m] - mx);
                sum += ev;
                u64 ee; PK(ee, ev, ev);
                const float* vr = X + m*68 + h8;
                ulonglong2 va = *(const ulonglong2*)vr;
                ulonglong2 vb = *(const ulonglong2*)(vr + 4);
                FMA2(c01, ee, va.x); FMA2(c23, ee, va.y);
                FMA2(c45, ee, vb.x); FMA2(c67, ee, vb.y);
            }
            float inv = 1.f / sum;
            float c0,c1,c2,c3,c4,c5,c6,c7;
            UNPK(c0,c1,c01); UNPK(c2,c3,c23); UNPK(c4,c5,c45); UNPK(c6,c7,c67);
            float4 o1 = make_float4(c0*inv, c1*inv, c2*inv, c3*inv);
            float4 o2 = make_float4(c4*inv, c5*inv, c6*inv, c7*inv);
            *(float4*)qr       = o1;   // CTX into Q slot (race-free)
            *(float4*)(qr + 4) = o2;
        }
    }
    __syncthreads();

    // ---- mo (W1): CB -> T with +geo +residual; prefetch out_w -> W0 ----
    {
        float4 pf4[4]; pre_ld(out_w, 64, pf4, tid);
        gemm_mo2e(CB0, CB1, W1, mo_b, PF0, PF1, T0, T1, tid);
        pre_st(W0, pf4, tid);
        __syncthreads();
    }

    // ---- LayerNorm over C (in place in T), both elements ----
    #pragma unroll
    for (int e = 0; e < 2; e++) {
        float* T = e ? T1 : T0;
        int n = tid >> 2, g = tid & 3;
        float* hr = T + n*68 + g*16;
        float4 v0 = *(const float4*)(hr);
        float4 v1 = *(const float4*)(hr + 4);
        float4 v2 = *(const float4*)(hr + 8);
        float4 v3 = *(const float4*)(hr + 12);
        float s  = v0.x+v0.y+v0.z+v0.w + v1.x+v1.y+v1.z+v1.w
                 + v2.x+v2.y+v2.z+v2.w + v3.x+v3.y+v3.z+v3.w;
        float s2 = v0.x*v0.x+v0.y*v0.y+v0.z*v0.z+v0.w*v0.w
                 + v1.x*v1.x+v1.y*v1.y+v1.z*v1.z+v1.w*v1.w
                 + v2.x*v2.x+v2.y*v2.y+v2.z*v2.z+v2.w*v2.w
                 + v3.x*v3.x+v3.y*v3.y+v3.z*v3.z+v3.w*v3.w;
        s  += __shfl_xor_sync(0xffffffffu, s, 1);
        s  += __shfl_xor_sync(0xffffffffu, s, 2);
        s2 += __shfl_xor_sync(0xffffffffu, s2, 1);
        s2 += __shfl_xor_sync(0xffffffffu, s2, 2);
        float mu  = s * 0.015625f;
        float var = s2 * 0.015625f - mu*mu;
        float r = rsqrtf(var + 1e-5f);
        int cb = g*16;
        float4 g0 = __ldg((const float4*)(ln_g + cb));
        float4 g1 = __ldg((const float4*)(ln_g + cb + 4));
        float4 g2 = __ldg((const float4*)(ln_g + cb + 8));
        float4 g3 = __ldg((const float4*)(ln_g + cb + 12));
        float4 b0 = __ldg((const float4*)(ln_b + cb));
        float4 b1 = __ldg((const float4*)(ln_b + cb + 4));
        float4 b2 = __ldg((const float4*)(ln_b + cb + 8));
        float4 b3 = __ldg((const float4*)(ln_b + cb + 12));
        hr[0]  = (v0.x-mu)*r*g0.x + b0.x;  hr[1]  = (v0.y-mu)*r*g0.y + b0.y;
        hr[2]  = (v0.z-mu)*r*g0.z + b0.z;  hr[3]  = (v0.w-mu)*r*g0.w + b0.w;
        hr[4]  = (v1.x-mu)*r*g1.x + b1.x;  hr[5]  = (v1.y-mu)*r*g1.y + b1.y;
        hr[6]  = (v1.z-mu)*r*g1.z + b1.z;  hr[7]  = (v1.w-mu)*r*g1.w + b1.w;
        hr[8]  = (v2.x-mu)*r*g2.x + b2.x;  hr[9]  = (v2.y-mu)*r*g2.y + b2.y;
        hr[10] = (v2.z-mu)*r*g2.z + b2.z;  hr[11] = (v2.w-mu)*r*g2.w + b2.w;
        hr[12] = (v3.x-mu)*r*g3.x + b3.x;  hr[13] = (v3.y-mu)*r*g3.y + b3.y;
        hr[14] = (v3.z-mu)*r*g3.z + b3.z;  hr[15] = (v3.w-mu)*r*g3.w + b3.w;
    }
    __syncthreads();

    // ---- final projection: straight to global (transposed), both elements ----
    gemm_out2e(T0, T1, W0, out_b,
               out + (size_t)(2*b)   * 4096,
               out + (size_t)(2*b+1) * 4096, tid);
}

// ---------------- launch ----------------
extern "C" void kernel_launch(void* const* d_in, const int* in_sizes, int n_in,
                              void* d_out, int out_size)
{
    const float* x         = (const float*)d_in[0];
    const float* points    = (const float*)d_in[1];
    const float* conv1_w   = (const float*)d_in[2];
    const float* conv1_b   = (const float*)d_in[3];
    const float* conv2_w   = (const float*)d_in[4];
    const float* conv2_b   = (const float*)d_in[5];
    const float* pattern   = (const float*)d_in[6];
    const float* pm1_w     = (const float*)d_in[7];
    const float* pm1_b     = (const float*)d_in[8];
    const float* pm2_w     = (const float*)d_in[9];
    const float* pm2_b     = (const float*)d_in[10];
    const float* q_w       = (const float*)d_in[11];
    const float* q_b       = (const float*)d_in[12];
    const float* k_w       = (const float*)d_in[13];
    const float* k_b       = (const float*)d_in[14];
    const float* v_w       = (const float*)d_in[15];
    const float* v_b       = (const float*)d_in[16];
    const float* in_w      = (const float*)d_in[17];
    const float* in_b      = (const float*)d_in[18];
    const float* mo_w      = (const float*)d_in[19];
    const float* mo_b      = (const float*)d_in[20];
    const float* out_w     = (const float*)d_in[21];
    const float* out_b     = (const float*)d_in[22];
    const float* ln_g      = (const float*)d_in[23];
    const float* ln_b      = (const float*)d_in[24];
    const int*   adjacency = (const int*)d_in[25];

    int B = in_sizes[0] / 4096;
    int B2 = B / 2;
    size_t smem = SMEM_FLOATS * sizeof(float);
    cudaFuncSetAttribute(esa_main_kernel, cudaFuncAttributeMaxDynamicSharedMemorySize, (int)smem);

    esa_prep_kernel<<<24, NT>>>(points, adjacency, in_w, in_b, pattern, pm1_w, pm1_b,
                                q_w, q_b, k_w, k_b, v_w, v_b);
    esa_main_kernel<<<B2, NT, smem>>>(x, conv1_w, conv1_b, conv2_w, conv2_b,
                                      pm1_w, pm2_w, pm2_b, mo_w, mo_b,
                                      out_w, out_b, ln_g, ln_b, (float*)d_out);
}

// round 8
// speedup vs baseline: 1.0020x; 1.0020x over previous
#include <cuda_runtime.h>
#include <math.h>

#define NT 256
typedef unsigned long long u64;

// f32x2 packed math (Blackwell): two fp32 FMAs per instruction
#define FMA2(d,a,b)  asm("fma.rn.f32x2 %0, %1, %2, %0;" : "+l"(d) : "l"(a), "l"(b))
#define UNPK(lo,hi,p) asm("mov.b64 {%0,%1}, %2;" : "=f"(lo), "=f"(hi) : "l"(p))
#define PK(p,lo,hi)   asm("mov.b64 %0, {%1,%2};" : "=l"(p) : "f"(lo), "f"(hi))

// ---------------- device scratch ----------------
__device__ __align__(16) float g_geo[4096];
__device__ __align__(16) float g_p16[4096];   // pattern part of pm1 + pm1_b per (n,j)
__device__ __align__(16) float g_wq[4096];
__device__ __align__(16) float g_wk[4096];
__device__ __align__(16) float g_wv[4096];
__device__ __align__(16) float g_bq[64];
__device__ __align__(16) float g_bk[64];
__device__ __align__(16) float g_bv[64];

// ---------------- prep: geo, P16, fused QKV weights ----------------
__global__ void esa_prep_kernel(const float* __restrict__ points,
                                const int*   __restrict__ adjacency,
                                const float* __restrict__ in_w,
                                const float* __restrict__ in_b,
                                const float* __restrict__ pattern,
                                const float* __restrict__ pm1_w,
                                const float* __restrict__ pm1_b,
                                const float* __restrict__ q_w, const float* __restrict__ q_b,
                                const float* __restrict__ k_w, const float* __restrict__ k_b,
                                const float* __restrict__ v_w, const float* __restrict__ v_b)
{
    const int gtid = blockIdx.x * blockDim.x + threadIdx.x;
    const int gstride = gridDim.x * blockDim.x;
    const float scale = 0.3535533905932738f; // 1/sqrt(8)

    for (int idx = gtid; idx < 4096; idx += gstride) {
        int n = idx >> 6, m = idx & 63;
        float dx = points[n*3+0] - points[m*3+0];
        float dy = points[n*3+1] - points[m*3+1];
        float dz = points[n*3+2] - points[m*3+2];
        float dist = sqrtf(dx*dx + dy*dy + dz*dz + 1e-12f);
        g_geo[idx] = (adjacency[idx] > 0) ? 0.5f : (-0.1f / (1.0f + dist));
    }
    for (int idx = gtid; idx < 4096; idx += gstride) {
        int n = idx >> 6, j = idx & 63;
        float s = pm1_b[j];
        const float* wr = pm1_w + j*80 + 64;
        const float* pr = pattern + n*16;
        #pragma unroll
        for (int p = 0; p < 16; p++) s += pr[p] * wr[p];
        g_p16[idx] = s;
    }
    for (int idx = gtid; idx < 3*4096; idx += gstride) {
        int which = idx >> 12;
        int o = (idx >> 6) & 63;
        int u = idx & 63;
        const float* wi = in_w + which*4096 + o*64;
        const float* wx = (which==0) ? q_w : (which==1) ? k_w : v_w;
        float s = 0.f;
        #pragma unroll 4
        for (int t = 0; t < 64; t++) s += wi[t] * wx[t*64 + u];
        if (which == 0) s *= scale;
        float* dst = (which==0) ? g_wq : (which==1) ? g_wk : g_wv;
        dst[o*64 + u] = s;
    }
    for (int idx = gtid; idx < 192; idx += gstride) {
        int which = idx >> 6, o = idx & 63;
        const float* wi = in_w + which*4096 + o*64;
        const float* bx = (which==0) ? q_b : (which==1) ? k_b : v_b;
        float s = in_b[which*64 + o];
        for (int t = 0; t < 64; t++) s += wi[t] * bx[t];
        if (which == 0) s *= scale;
        float* dst = (which==0) ? g_bq : (which==1) ? g_bk : g_bv;
        dst[o] = s;
    }
}

// ---------------- weight staging (all 256 threads, 4 float4 each) ----------------
__device__ __forceinline__ void pre_ld(const float* __restrict__ src, int sstr,
                                       float4* r, int tid) {
    #pragma unroll
    for (int i = 0; i < 4; i++) {
        int idx4 = tid + i*NT;
        int rr = idx4 >> 4, cc = (idx4 & 15) << 2;
        r[i] = __ldg((const float4*)(src + rr*sstr + cc));
    }
}
__device__ __forceinline__ void pre_st(float* __restrict__ Wd, const float4* r, int tid) {
    #pragma unroll
    for (int i = 0; i < 4; i++) {
        int idx4 = tid + i*NT;
        int rr = idx4 >> 4, cc = (idx4 & 15) << 2;
        *(float4*)(Wd + rr*68 + cc) = r[i];
    }
}

// ---------------- 2-element f32x2 GEMM: b registers shared across elements ----------
// per element: rows n0..n0+3 (n0=(tid>>4)*4), cols j0+16j (j0=tid&15)
template<bool RELU, bool BIASMAT>
__device__ __forceinline__ void gemm2e(const float* __restrict__ in0,
                                       const float* __restrict__ in1, int sin,
                                       const float* __restrict__ W,
                                       const float* __restrict__ bias,
                                       float* __restrict__ out0,
                                       float* __restrict__ out1, int so, int tid)
{
    const int n0 = (tid >> 4) << 2;
    const int j0 = tid & 15;
    u64 ac0[4][4], ac1[4][4];
    #pragma unroll
    for (int i = 0; i < 4; i++)
        #pragma unroll
        for (int j = 0; j < 4; j++) { ac0[i][j] = 0ull; ac1[i][j] = 0ull; }

    const float* ap0 = in0 + n0*sin;
    const float* ap1 = in1 + n0*sin;
    const float* wp  = W + j0*68;
    #pragma unroll 4
    for (int k = 0; k < 64; k += 4) {
        ulonglong2 b[4];
        b[0] = *(const ulonglong2*)(wp + k);
        b[1] = *(const ulonglong2*)(wp + 16*68 + k);
        b[2] = *(const ulonglong2*)(wp + 32*68 + k);
        b[3] = *(const ulonglong2*)(wp + 48*68 + k);
        #pragma unroll
        for (int i = 0; i < 4; i++) {
            ulonglong2 a0 = *(const ulonglong2*)(ap0 + i*sin + k);
            ulonglong2 a1 = *(const ulonglong2*)(ap1 + i*sin + k);
            #pragma unroll
            for (int j = 0; j < 4; j++) {
                FMA2(ac0[i][j], a0.x, b[j].x);
                FMA2(ac0[i][j], a0.y, b[j].y);
                FMA2(ac1[i][j], a1.x, b[j].x);
                FMA2(ac1[i][j], a1.y, b[j].y);
            }
        }
    }
    #pragma unroll
    for (int j = 0; j < 4; j++) {
        int jj = j0 + 16*j;
        float bj = BIASMAT ? 0.f : __ldg(bias + jj);
        #pragma unroll
        for (int i = 0; i < 4; i++) {
            int row = n0 + i;
            float bm = BIASMAT ? __ldg(bias + row*64 + jj) : bj;
            float lo, hi;
            UNPK(lo, hi, ac0[i][j]);
            float v0 = lo + hi + bm;
            UNPK(lo, hi, ac1[i][j]);
            float v1 = lo + hi + bm;
            if (RELU) { v0 = fmaxf(v0, 0.f); v1 = fmaxf(v1, 0.f); }
            out0[row*so + jj] = v0;
            out1[row*so + jj] = v1;
        }
    }
}

// mo projection: fused +geo +residual epilogue, 2 elements
__device__ __forceinline__ void gemm_mo2e(const float* __restrict__ in0,
                                          const float* __restrict__ in1,
                                          const float* __restrict__ W,
                                          const float* __restrict__ mo_b,
                                          const float* __restrict__ pf0,
                                          const float* __restrict__ pf1,
                                          float* __restrict__ out0,
                                          float* __restrict__ out1, int tid)
{
    const int n0 = (tid >> 4) << 2;
    const int j0 = tid & 15;
    u64 ac0[4][4], ac1[4][4];
    #pragma unroll
    for (int i = 0; i < 4; i++)
        #pragma unroll
        for (int j = 0; j < 4; j++) { ac0[i][j] = 0ull; ac1[i][j] = 0ull; }

    const float* ap0 = in0 + n0*68;
    const float* ap1 = in1 + n0*68;
    const float* wp  = W + j0*68;
    #pragma unroll 4
    for (int k = 0; k < 64; k += 4) {
        ulonglong2 b[4];
        b[0] = *(const ulonglong2*)(wp + k);
        b[1] = *(const ulonglong2*)(wp + 16*68 + k);
        b[2] = *(const ulonglong2*)(wp + 32*68 + k);
        b[3] = *(const ulonglong2*)(wp + 48*68 + k);
        #pragma unroll
        for (int i = 0; i < 4; i++) {
            ulonglong2 a0 = *(const ulonglong2*)(ap0 + i*68 + k);
            ulonglong2 a1 = *(const ulonglong2*)(ap1 + i*68 + k);
            #pragma unroll
            for (int j = 0; j < 4; j++) {
                FMA2(ac0[i][j], a0.x, b[j].x);
                FMA2(ac0[i][j], a0.y, b[j].y);
                FMA2(ac1[i][j], a1.x, b[j].x);
                FMA2(ac1[i][j], a1.y, b[j].y);
            }
        }
    }
    #pragma unroll
    for (int j = 0; j < 4; j++) {
        int jj = j0 + 16*j;
        float bj = __ldg(mo_b + jj);
        #pragma unroll
        for (int i = 0; i < 4; i++) {
            int row = n0 + i;
            float gg = __ldg(g_geo + row*64 + jj) + bj;
            float lo, hi;
            UNPK(lo, hi, ac0[i][j]);
            out0[row*68 + jj] = lo + hi + gg + pf0[row*68 + jj];
            UNPK(lo, hi, ac1[i][j]);
            out1[row*68 + jj] = lo + hi + gg + pf1[row*68 + jj];
        }
    }
}

// final projection: straight to global, transposed layout (out[c][n]), 2 elements
__device__ __forceinline__ void gemm_out2e(const float* __restrict__ in0,
                                           const float* __restrict__ in1,
                                           const float* __restrict__ W,
                                           const float* __restrict__ bias,
                                           float* __restrict__ og0,
                                           float* __restrict__ og1, int tid)
{
    const int n0 = (tid >> 4) << 2;
    const int j0 = tid & 15;
    u64 ac0[4][4], ac1[4][4];
    #pragma unroll
    for (int i = 0; i < 4; i++)
        #pragma unroll
        for (int j = 0; j < 4; j++) { ac0[i][j] = 0ull; ac1[i][j] = 0ull; }

    const float* ap0 = in0 + n0*68;
    const float* ap1 = in1 + n0*68;
    const float* wp  = W + j0*68;
    #pragma unroll 4
    for (int k = 0; k < 64; k += 4) {
        ulonglong2 b[4];
        b[0] = *(const ulonglong2*)(wp + k);
        b[1] = *(const ulonglong2*)(wp + 16*68 + k);
        b[2] = *(const ulonglong2*)(wp + 32*68 + k);
        b[3] = *(const ulonglong2*)(wp + 48*68 + k);
        #pragma unroll
        for (int i = 0; i < 4; i++) {
            ulonglong2 a0 = *(const ulonglong2*)(ap0 + i*68 + k);
            ulonglong2 a1 = *(const ulonglong2*)(ap1 + i*68 + k);
            #pragma unroll
            for (int j = 0; j < 4; j++) {
                FMA2(ac0[i][j], a0.x, b[j].x);
                FMA2(ac0[i][j], a0.y, b[j].y);
                FMA2(ac1[i][j], a1.x, b[j].x);
                FMA2(ac1[i][j], a1.y, b[j].y);
            }
        }
    }
    #pragma unroll
    for (int j = 0; j < 4; j++) {
        int jj = j0 + 16*j;
        float bj = __ldg(bias + jj);
        #pragma unroll
        for (int i = 0; i < 4; i++) {
            int row = n0 + i;
            float lo, hi;
            UNPK(lo, hi, ac0[i][j]);
            og0[jj*64 + row] = lo + hi + bj;
            UNPK(lo, hi, ac1[i][j]);
            og1[jj*64 + row] = lo + hi + bj;
        }
    }
}

// conv tap: 4 outputs with shifted 3-tap window, accs named
#define CONVTAP(XP, CC, W0m, W1m, W2m, q0, q1, q2, q3) { \
    const float* xr = (XP) + (CC)*68 + base; \
    float4 xv = *(const float4*)xr; float2 xt = *(const float2*)(xr+4); \
    q0 += (W0m)*xv.x + (W1m)*xv.y + (W2m)*xv.z; \
    q1 += (W0m)*xv.y + (W1m)*xv.z + (W2m)*xv.w; \
    q2 += (W0m)*xv.z + (W1m)*xv.w + (W2m)*xt.x; \
    q3 += (W0m)*xv.w + (W1m)*xt.x + (W2m)*xt.y; }

// gemm phase: all threads compute, weights for NEXT phase prefetched around it
#define GPHASE(RELU, BM, IN0, IN1, SIN, WCUR, BIAS, OUT0, OUT1, SO, NXT, NSTR, WNXT) { \
    float4 pf4[4]; pre_ld(NXT, NSTR, pf4, tid); \
    gemm2e<RELU, BM>(IN0, IN1, SIN, WCUR, BIAS, OUT0, OUT1, SO, tid); \
    pre_st(WNXT, pf4, tid); \
    __syncthreads(); }

// ---------------- main kernel: one CTA per 2 batch elements ----------------
// smem (floats): W0 0(4352) | W1 4352(4352) | then per element e (base 8704+e*18496):
//   X +0(4352) | Y1 +4352(1088) | CB +5440(4352) | T +9792(4352) | PF +14144(4352)
#define SMEM_FLOATS 45696

__global__ void __launch_bounds__(NT, 1)
esa_main_kernel(const float* __restrict__ x,
                const float* __restrict__ conv1_w, const float* __restrict__ conv1_b,
                const float* __restrict__ conv2_w, const float* __restrict__ conv2_b,
                const float* __restrict__ pm1_w,
                const float* __restrict__ pm2_w, const float* __restrict__ pm2_b,
                const float* __restrict__ mo_w,  const float* __restrict__ mo_b,
                const float* __restrict__ out_w, const float* __restrict__ out_b,
                const float* __restrict__ ln_g,  const float* __restrict__ ln_b,
                float* __restrict__ out)
{
    extern __shared__ float sm[];
    const int tid = threadIdx.x;
    const int b = blockIdx.x;
    float* W0 = sm;
    float* W1 = sm + 4352;
    float* X0  = sm + 8704;              float* X1  = X0 + 18496;
    float* Y10 = X0 + 4352;              float* Y11 = Y10 + 18496;
    float* CB0 = X0 + 5440;              float* CB1 = CB0 + 18496;
    float* T0  = X0 + 9792;              float* T1  = T0 + 18496;
    float* PF0 = X0 + 14144;             float* PF1 = PF0 + 18496;

    // ---- load x for both elements + stage pm1 (cols 0..63) into W0 ----
    {
        float4 pw[4]; pre_ld(pm1_w, 80, pw, tid);
        const float* xg = x + (size_t)(2*b) * 4096;
        for (int idx4 = tid; idx4 < 2048; idx4 += NT) {
            float4 v = __ldg((const float4*)xg + idx4);
            int e = idx4 >> 10, i = idx4 & 1023;
            int c = i >> 4, n = (i & 15) << 2;
            float* rr = (e ? X1 : X0) + c*68 + 1 + n;
            rr[0] = v.x; rr[1] = v.y; rr[2] = v.z; rr[3] = v.w;
        }
        pre_st(W0, pw, tid);
        if (tid < 64) {
            X0[tid*68] = 0.f; X0[tid*68 + 65] = 0.f;
            X1[tid*68] = 0.f; X1[tid*68 + 65] = 0.f;
        }
        if (tid < 16) {
            Y10[tid*68] = 0.f; Y10[tid*68 + 65] = 0.f;
            Y11[tid*68] = 0.f; Y11[tid*68 + 65] = 0.f;
        }
    }
    __syncthreads();

    // ---- 4-scale conv stack, both elements share weight registers ----
    for (int s = 0; s < 4; s++) {
        {
            int o = tid >> 4, nq = tid & 15, base = nq*4;
            const float* wr = conv1_w + s*3072 + o*192;
            float a0=0.f,a1=0.f,a2=0.f,a3=0.f, c0=0.f,c1=0.f,c2=0.f,c3=0.f;
            #pragma unroll 4
            for (int c = 0; c < 64; c += 4) {
                float4 wA = __ldg((const float4*)(wr + c*3));
                float4 wB = __ldg((const float4*)(wr + c*3 + 4));
                float4 wC = __ldg((const float4*)(wr + c*3 + 8));
                CONVTAP(X0, c+0, wA.x, wA.y, wA.z, a0,a1,a2,a3);
                CONVTAP(X0, c+1, wA.w, wB.x, wB.y, a0,a1,a2,a3);
                CONVTAP(X0, c+2, wB.z, wB.w, wC.x, a0,a1,a2,a3);
                CONVTAP(X0, c+3, wC.y, wC.z, wC.w, a0,a1,a2,a3);
                CONVTAP(X1, c+0, wA.x, wA.y, wA.z, c0,c1,c2,c3);
                CONVTAP(X1, c+1, wA.w, wB.x, wB.y, c0,c1,c2,c3);
                CONVTAP(X1, c+2, wB.z, wB.w, wC.x, c0,c1,c2,c3);
                CONVTAP(X1, c+3, wC.y, wC.z, wC.w, c0,c1,c2,c3);
            }
            float bb = __ldg(conv1_b + s*16 + o);
            float* yr0 = Y10 + o*68 + 1 + base;
            float* yr1 = Y11 + o*68 + 1 + base;
            yr0[0]=fmaxf(a0+bb,0.f); yr0[1]=fmaxf(a1+bb,0.f); yr0[2]=fmaxf(a2+bb,0.f); yr0[3]=fmaxf(a3+bb,0.f);
            yr1[0]=fmaxf(c0+bb,0.f); yr1[1]=fmaxf(c1+bb,0.f); yr1[2]=fmaxf(c2+bb,0.f); yr1[3]=fmaxf(c3+bb,0.f);
        }
        __syncthreads();
        {
            int o = tid >> 4, nq = tid & 15, base = nq*4;
            const float* wr = conv2_w + s*768 + o*48;
            float a0=0.f,a1=0.f,a2=0.f,a3=0.f, c0=0.f,c1=0.f,c2=0.f,c3=0.f;
            #pragma unroll
            for (int c = 0; c < 16; c += 4) {
                float4 wA = __ldg((const float4*)(wr + c*3));
                float4 wB = __ldg((const float4*)(wr + c*3 + 4));
                float4 wC = __ldg((const float4*)(wr + c*3 + 8));
                CONVTAP(Y10, c+0, wA.x, wA.y, wA.z, a0,a1,a2,a3);
                CONVTAP(Y10, c+1, wA.w, wB.x, wB.y, a0,a1,a2,a3);
                CONVTAP(Y10, c+2, wB.z, wB.w, wC.x, a0,a1,a2,a3);
                CONVTAP(Y10, c+3, wC.y, wC.z, wC.w, a0,a1,a2,a3);
                CONVTAP(Y11, c+0, wA.x, wA.y, wA.z, c0,c1,c2,c3);
                CONVTAP(Y11, c+1, wA.w, wB.x, wB.y, c0,c1,c2,c3);
                CONVTAP(Y11, c+2, wB.z, wB.w, wC.x, c0,c1,c2,c3);
                CONVTAP(Y11, c+3, wC.y, wC.z, wC.w, c0,c1,c2,c3);
            }
            float bb = __ldg(conv2_b + s*16 + o);
            int ch = s*16 + o;
            CB0[(base+0)*68+ch]=fmaxf(a0+bb,0.f); CB0[(base+1)*68+ch]=fmaxf(a1+bb,0.f);
            CB0[(base+2)*68+ch]=fmaxf(a2+bb,0.f); CB0[(base+3)*68+ch]=fmaxf(a3+bb,0.f);
            CB1[(base+0)*68+ch]=fmaxf(c0+bb,0.f); CB1[(base+1)*68+ch]=fmaxf(c1+bb,0.f);
            CB1[(base+2)*68+ch]=fmaxf(c2+bb,0.f); CB1[(base+3)*68+ch]=fmaxf(c3+bb,0.f);
        }
        __syncthreads();
    }

    // ---- GEMM chain, weights double-buffered, b regs shared across elements ----
    GPHASE(true,  true,  CB0, CB1, 68, W0, g_p16, T0,  T1,  68, pm2_w, 64, W1);  // pm1
    GPHASE(false, false, T0,  T1,  68, W1, pm2_b, PF0, PF1, 68, g_wq,  64, W0);  // pm2
    GPHASE(false, false, PF0, PF1, 68, W0, g_bq,  CB0, CB1, 68, g_wk,  64, W1);  // Q
    GPHASE(false, false, PF0, PF1, 68, W1, g_bk,  T0,  T1,  68, g_wv,  64, W0);  // K
    GPHASE(false, false, PF0, PF1, 68, W0, g_bv,  X0,  X1,  68, mo_w,  64, W1);  // V

    // ---- attention: both elements sequentially; thread = (n, head-block) ----
    #pragma unroll
    for (int e = 0; e < 2; e++) {
        float* CB = e ? CB1 : CB0;
        float* T  = e ? T1  : T0;
        float* X  = e ? X1  : X0;
        const int n  = tid & 63;
        const int hb = tid >> 6;
        #pragma unroll
        for (int it = 0; it < 2; it++) {
            const int h8 = (hb + 4*it) * 8;
            float* qr = CB + n*68 + h8;
            ulonglong2 qa = *(const ulonglong2*)qr;
            ulonglong2 qb = *(const ulonglong2*)(qr + 4);
            float sc[64];
            float mx = -3.0e38f;
            #pragma unroll
            for (int m = 0; m < 64; m++) {
                const float* kr = T + m*68 + h8;
                ulonglong2 ka = *(const ulonglong2*)kr;
                ulonglong2 kb = *(const ulonglong2*)(kr + 4);
                u64 d = 0ull;
                FMA2(d, qa.x, ka.x); FMA2(d, qa.y, ka.y);
                FMA2(d, qb.x, kb.x); FMA2(d, qb.y, kb.y);
                float lo, hi; UNPK(lo, hi, d);
                float sv = lo + hi;
                sc[m] = sv; mx = fmaxf(mx, sv);
            }
            u64 c01 = 0ull, c23 = 0ull, c45 = 0ull, c67 = 0ull;
            float sum = 0.f;
            #pragma unroll
            for (int m = 0; m < 64; m++) {
                float ev = __expf(sc[m] - mx);
                sum += ev;
                u64 ee; PK(ee, ev, ev);
                const float* vr = X + m*68 + h8;
                ulonglong2 va = *(const ulonglong2*)vr;
                ulonglong2 vb = *(const ulonglong2*)(vr + 4);
                FMA2(c01, ee, va.x); FMA2(c23, ee, va.y);
                FMA2(c45, ee, vb.x); FMA2(c67, ee, vb.y);
            }
            float inv = 1.f / sum;
            float c0,c1,c2,c3,c4,c5,c6,c7;
            UNPK(c0,c1,c01); UNPK(c2,c3,c23); UNPK(c4,c5,c45); UNPK(c6,c7,c67);
            float4 o1 = make_float4(c0*inv, c1*inv, c2*inv, c3*inv);
            float4 o2 = make_float4(c4*inv, c5*inv, c6*inv, c7*inv);
            *(float4*)qr       = o1;   // CTX into Q slot (race-free)
            *(float4*)(qr + 4) = o2;
        }
    }
    __syncthreads();

    // ---- mo (W1): CB -> T with +geo +residual; prefetch out_w -> W0 ----
    {
        float4 pf4[4]; pre_ld(out_w, 64, pf4, tid);
        gemm_mo2e(CB0, CB1, W1, mo_b, PF0, PF1, T0, T1, tid);
        pre_st(W0, pf4, tid);
        __syncthreads();
    }

    // ---- LayerNorm over C (in place in T), both elements ----
    #pragma unroll
    for (int e = 0; e < 2; e++) {
        float* T = e ? T1 : T0;
        int n = tid >> 2, g = tid & 3;
        float* hr = T + n*68 + g*16;
        float4 v0 = *(const float4*)(hr);
        float4 v1 = *(const float4*)(hr + 4);
        float4 v2 = *(const float4*)(hr + 8);
        float4 v3 = *(const float4*)(hr + 12);
        float s  = v0.x+v0.y+v0.z+v0.w + v1.x+v1.y+v1.z+v1.w
                 + v2.x+v2.y+v2.z+v2.w + v3.x+v3.y+v3.z+v3.w;
        float s2 = v0.x*v0.x+v0.y*v0.y+v0.z*v0.z+v0.w*v0.w
                 + v1.x*v1.x+v1.y*v1.y+v1.z*v1.z+v1.w*v1.w
                 + v2.x*v2.x+v2.y*v2.y+v2.z*v2.z+v2.w*v2.w
                 + v3.x*v3.x+v3.y*v3.y+v3.z*v3.z+v3.w*v3.w;
        s  += __shfl_xor_sync(0xffffffffu, s, 1);
        s  += __shfl_xor_sync(0xffffffffu, s, 2);
        s2 += __shfl_xor_sync(0xffffffffu, s2, 1);
        s2 += __shfl_xor_sync(0xffffffffu, s2, 2);
        float mu  = s * 0.015625f;
        float var = s2 * 0.015625f - mu*mu;
        float r = rsqrtf(var + 1e-5f);
        int cb = g*16;
        float4 g0 = __ldg((const float4*)(ln_g + cb));
        float4 g1 = __ldg((const float4*)(ln_g + cb + 4));
        float4 g2 = __ldg((const float4*)(ln_g + cb + 8));
        float4 g3 = __ldg((const float4*)(ln_g + cb + 12));
        float4 b0 = __ldg((const float4*)(ln_b + cb));
        float4 b1 = __ldg((const float4*)(ln_b + cb + 4));
        float4 b2 = __ldg((const float4*)(ln_b + cb + 8));
        float4 b3 = __ldg((const float4*)(ln_b + cb + 12));
        hr[0]  = (v0.x-mu)*r*g0.x + b0.x;  hr[1]  = (v0.y-mu)*r*g0.y + b0.y;
        hr[2]  = (v0.z-mu)*r*g0.z + b0.z;  hr[3]  = (v0.w-mu)*r*g0.w + b0.w;
        hr[4]  = (v1.x-mu)*r*g1.x + b1.x;  hr[5]  = (v1.y-mu)*r*g1.y + b1.y;
        hr[6]  = (v1.z-mu)*r*g1.z + b1.z;  hr[7]  = (v1.w-mu)*r*g1.w + b1.w;
        hr[8]  = (v2.x-mu)*r*g2.x + b2.x;  hr[9]  = (v2.y-mu)*r*g2.y + b2.y;
        hr[10] = (v2.z-mu)*r*g2.z + b2.z;  hr[11] = (v2.w-mu)*r*g2.w + b2.w;
        hr[12] = (v3.x-mu)*r*g3.x + b3.x;  hr[13] = (v3.y-mu)*r*g3.y + b3.y;
        hr[14] = (v3.z-mu)*r*g3.z + b3.z;  hr[15] = (v3.w-mu)*r*g3.w + b3.w;
    }
    __syncthreads();

    // ---- final projection: straight to global (transposed), both elements ----
    gemm_out2e(T0, T1, W0, out_b,
               out + (size_t)(2*b)   * 4096,
               out + (size_t)(2*b+1) * 4096, tid);
}

// ---------------- launch ----------------
extern "C" void kernel_launch(void* const* d_in, const int* in_sizes, int n_in,
                              void* d_out, int out_size)
{
    const float* x         = (const float*)d_in[0];
    const float* points    = (const float*)d_in[1];
    const float* conv1_w   = (const float*)d_in[2];
    const float* conv1_b   = (const float*)d_in[3];
    const float* conv2_w   = (const float*)d_in[4];
    const float* conv2_b   = (const float*)d_in[5];
    const float* pattern   = (const float*)d_in[6];
    const float* pm1_w     = (const float*)d_in[7];
    const float* pm1_b     = (const float*)d_in[8];
    const float* pm2_w     = (const float*)d_in[9];
    const float* pm2_b     = (const float*)d_in[10];
    const float* q_w       = (const float*)d_in[11];
    const float* q_b       = (const float*)d_in[12];
    const float* k_w       = (const float*)d_in[13];
    const float* k_b       = (const float*)d_in[14];
    const float* v_w       = (const float*)d_in[15];
    const float* v_b       = (const float*)d_in[16];
    const float* in_w      = (const float*)d_in[17];
    const float* in_b      = (const float*)d_in[18];
    const float* mo_w      = (const float*)d_in[19];
    const float* mo_b      = (const float*)d_in[20];
    const float* out_w     = (const float*)d_in[21];
    const float* out_b     = (const float*)d_in[22];
    const float* ln_g      = (const float*)d_in[23];
    const float* ln_b      = (const float*)d_in[24];
    const int*   adjacency = (const int*)d_in[25];

    int B = in_sizes[0] / 4096;
    int B2 = B / 2;
    size_t smem = SMEM_FLOATS * sizeof(float);
    cudaFuncSetAttribute(esa_main_kernel, cudaFuncAttributeMaxDynamicSharedMemorySize, (int)smem);

    esa_prep_kernel<<<24, NT>>>(points, adjacency, in_w, in_b, pattern, pm1_w, pm1_b,
                                q_w, q_b, k_w, k_b, v_w, v_b);
    esa_main_kernel<<<B2, NT, smem>>>(x, conv1_w, conv1_b, conv2_w, conv2_b,
                                      pm1_w, pm2_w, pm2_b, mo_w, mo_b,
                                      out_w, out_b, ln_g, ln_b, (float*)d_out);
}

// round 9
// speedup vs baseline: 1.0635x; 1.0614x over previous
#include <cuda_runtime.h>
#include <math.h>

#define NT 256
typedef unsigned long long u64;

// f32x2 packed math (Blackwell)
#define FMA2(d,a,b)  asm("fma.rn.f32x2 %0, %1, %2, %0;" : "+l"(d) : "l"(a), "l"(b))
#define MUL2(d,a,b)  asm("mul.rn.f32x2 %0, %1, %2;" : "=l"(d) : "l"(a), "l"(b))
#define UNPK(lo,hi,p) asm("mov.b64 {%0,%1}, %2;" : "=f"(lo), "=f"(hi) : "l"(p))
#define PK(p,lo,hi)   asm("mov.b64 %0, {%1,%2};" : "=l"(p) : "f"(lo), "f"(hi))

// ---------------- device scratch ----------------
__device__ __align__(16) float g_geo[4096];
__device__ __align__(16) float g_p16[4096];
__device__ __align__(16) float g_wq[4096];
__device__ __align__(16) float g_wk[4096];
__device__ __align__(16) float g_wv[4096];
__device__ __align__(16) float g_bq[64];
__device__ __align__(16) float g_bk[64];
__device__ __align__(16) float g_bv[64];

// ---------------- prep: geo, P16, fused QKV weights ----------------
__global__ void esa_prep_kernel(const float* __restrict__ points,
                                const int*   __restrict__ adjacency,
                                const float* __restrict__ in_w,
                                const float* __restrict__ in_b,
                                const float* __restrict__ pattern,
                                const float* __restrict__ pm1_w,
                                const float* __restrict__ pm1_b,
                                const float* __restrict__ q_w, const float* __restrict__ q_b,
                                const float* __restrict__ k_w, const float* __restrict__ k_b,
                                const float* __restrict__ v_w, const float* __restrict__ v_b)
{
    const int gtid = blockIdx.x * blockDim.x + threadIdx.x;
    const int gstride = gridDim.x * blockDim.x;
    const float scale = 0.3535533905932738f; // 1/sqrt(8)

    for (int idx = gtid; idx < 4096; idx += gstride) {
        int n = idx >> 6, m = idx & 63;
        float dx = points[n*3+0] - points[m*3+0];
        float dy = points[n*3+1] - points[m*3+1];
        float dz = points[n*3+2] - points[m*3+2];
        float dist = sqrtf(dx*dx + dy*dy + dz*dz + 1e-12f);
        g_geo[idx] = (adjacency[idx] > 0) ? 0.5f : (-0.1f / (1.0f + dist));
    }
    for (int idx = gtid; idx < 4096; idx += gstride) {
        int n = idx >> 6, j = idx & 63;
        float s = pm1_b[j];
        const float* wr = pm1_w + j*80 + 64;
        const float* pr = pattern + n*16;
        #pragma unroll
        for (int p = 0; p < 16; p++) s += pr[p] * wr[p];
        g_p16[idx] = s;
    }
    for (int idx = gtid; idx < 3*4096; idx += gstride) {
        int which = idx >> 12;
        int o = (idx >> 6) & 63;
        int u = idx & 63;
        const float* wi = in_w + which*4096 + o*64;
        const float* wx = (which==0) ? q_w : (which==1) ? k_w : v_w;
        float s = 0.f;
        #pragma unroll 4
        for (int t = 0; t < 64; t++) s += wi[t] * wx[t*64 + u];
        if (which == 0) s *= scale;
        float* dst = (which==0) ? g_wq : (which==1) ? g_wk : g_wv;
        dst[o*64 + u] = s;
    }
    for (int idx = gtid; idx < 192; idx += gstride) {
        int which = idx >> 6, o = idx & 63;
        const float* wi = in_w + which*4096 + o*64;
        const float* bx = (which==0) ? q_b : (which==1) ? k_b : v_b;
        float s = in_b[which*64 + o];
        for (int t = 0; t < 64; t++) s += wi[t] * bx[t];
        if (which == 0) s *= scale;
        float* dst = (which==0) ? g_bq : (which==1) ? g_bk : g_bv;
        dst[o] = s;
    }
}

// ---------------- weight staging ----------------
__device__ __forceinline__ void pre_ld(const float* __restrict__ src, int sstr,
                                       float4* r, int tid) {
    #pragma unroll
    for (int i = 0; i < 4; i++) {
        int idx4 = tid + i*NT;
        int rr = idx4 >> 4, cc = (idx4 & 15) << 2;
        r[i] = __ldg((const float4*)(src + rr*sstr + cc));
    }
}
__device__ __forceinline__ void pre_st(float* __restrict__ Wd, const float4* r, int tid) {
    #pragma unroll
    for (int i = 0; i < 4; i++) {
        int idx4 = tid + i*NT;
        int rr = idx4 >> 4, cc = (idx4 & 15) << 2;
        *(float4*)(Wd + rr*68 + cc) = r[i];
    }
}
// prefetch-warp version (stride-64 sources): 8 float4 per thread
__device__ __forceinline__ void stage_w_half(const float* __restrict__ src,
                                             float* __restrict__ Wd, int t2) {
    float4 r[8];
    #pragma unroll
    for (int i = 0; i < 8; i++) {
        int idx4 = t2 + i*128;
        int rr = idx4 >> 4, cc = (idx4 & 15) << 2;
        r[i] = __ldg((const float4*)(src + rr*64 + cc));
    }
    #pragma unroll
    for (int i = 0; i < 8; i++) {
        int idx4 = t2 + i*128;
        int rr = idx4 >> 4, cc = (idx4 & 15) << 2;
        *(float4*)(Wd + rr*68 + cc) = r[i];
    }
}

// ---------------- f32x2 GEMM, 4x8 tiles on 128 threads ----------------
template<bool RELU, bool BIASMAT>
__device__ __forceinline__ void gemm48(const float* __restrict__ in, int sin,
                                       const float* __restrict__ W,
                                       const float* __restrict__ bias,
                                       float* __restrict__ outp, int so, int tid)
{
    const int r  = tid >> 3;
    const int j0 = tid & 7;
    u64 acc[4][8];
    #pragma unroll
    for (int i = 0; i < 4; i++)
        #pragma unroll
        for (int j = 0; j < 8; j++) acc[i][j] = 0ull;

    const float* ap = in + r*sin;
    const float* wp = W + j0*68;
    #pragma unroll 4
    for (int k = 0; k < 64; k += 4) {
        ulonglong2 a[4];
        a[0] = *(const ulonglong2*)(ap + k);
        a[1] = *(const ulonglong2*)(ap + 16*sin + k);
        a[2] = *(const ulonglong2*)(ap + 32*sin + k);
        a[3] = *(const ulonglong2*)(ap + 48*sin + k);
        #pragma unroll
        for (int j = 0; j < 8; j++) {
            ulonglong2 b = *(const ulonglong2*)(wp + j*8*68 + k);
            #pragma unroll
            for (int i = 0; i < 4; i++) {
                FMA2(acc[i][j], a[i].x, b.x);
                FMA2(acc[i][j], a[i].y, b.y);
            }
        }
    }
    #pragma unroll
    for (int j = 0; j < 8; j++) {
        int jj = j0 + 8*j;
        float bj = BIASMAT ? 0.f : __ldg(bias + jj);
        #pragma unroll
        for (int i = 0; i < 4; i++) {
            int row = r + 16*i;
            float lo, hi; UNPK(lo, hi, acc[i][j]);
            float v = lo + hi + bj;
            if (BIASMAT) v += __ldg(bias + row*64 + jj);
            if (RELU) v = fmaxf(v, 0.f);
            outp[row*so + jj] = v;
        }
    }
}

__device__ __forceinline__ void gemm_mo48(const float* __restrict__ in,
                                          const float* __restrict__ W,
                                          const float* __restrict__ mo_b,
                                          const float* __restrict__ pf,
                                          float* __restrict__ outp, int tid)
{
    const int r  = tid >> 3;
    const int j0 = tid & 7;
    u64 acc[4][8];
    #pragma unroll
    for (int i = 0; i < 4; i++)
        #pragma unroll
        for (int j = 0; j < 8; j++) acc[i][j] = 0ull;

    const float* ap = in + r*68;
    const float* wp = W + j0*68;
    #pragma unroll 4
    for (int k = 0; k < 64; k += 4) {
        ulonglong2 a[4];
        a[0] = *(const ulonglong2*)(ap + k);
        a[1] = *(const ulonglong2*)(ap + 16*68 + k);
        a[2] = *(const ulonglong2*)(ap + 32*68 + k);
        a[3] = *(const ulonglong2*)(ap + 48*68 + k);
        #pragma unroll
        for (int j = 0; j < 8; j++) {
            ulonglong2 b = *(const ulonglong2*)(wp + j*8*68 + k);
            #pragma unroll
            for (int i = 0; i < 4; i++) {
                FMA2(acc[i][j], a[i].x, b.x);
                FMA2(acc[i][j], a[i].y, b.y);
            }
        }
    }
    #pragma unroll
    for (int j = 0; j < 8; j++) {
        int jj = j0 + 8*j;
        float bj = __ldg(mo_b + jj);
        #pragma unroll
        for (int i = 0; i < 4; i++) {
            int row = r + 16*i;
            float lo, hi; UNPK(lo, hi, acc[i][j]);
            outp[row*68 + jj] = lo + hi + bj + __ldg(g_geo + row*64 + jj) + pf[row*68 + jj];
        }
    }
}

__device__ __forceinline__ void gemm_out48(const float* __restrict__ in,
                                           const float* __restrict__ W,
                                           const float* __restrict__ bias,
                                           float* __restrict__ og, int tid)
{
    const int r  = tid >> 3;
    const int j0 = tid & 7;
    u64 acc[4][8];
    #pragma unroll
    for (int i = 0; i < 4; i++)
        #pragma unroll
        for (int j = 0; j < 8; j++) acc[i][j] = 0ull;

    const float* ap = in + r*68;
    const float* wp = W + j0*68;
    #pragma unroll 4
    for (int k = 0; k < 64; k += 4) {
        ulonglong2 a[4];
        a[0] = *(const ulonglong2*)(ap + k);
        a[1] = *(const ulonglong2*)(ap + 16*68 + k);
        a[2] = *(const ulonglong2*)(ap + 32*68 + k);
        a[3] = *(const ulonglong2*)(ap + 48*68 + k);
        #pragma unroll
        for (int j = 0; j < 8; j++) {
            ulonglong2 b = *(const ulonglong2*)(wp + j*8*68 + k);
            #pragma unroll
            for (int i = 0; i < 4; i++) {
                FMA2(acc[i][j], a[i].x, b.x);
                FMA2(acc[i][j], a[i].y, b.y);
            }
        }
    }
    #pragma unroll
    for (int j = 0; j < 8; j++) {
        int jj = j0 + 8*j;
        float bj = __ldg(bias + jj);
        #pragma unroll
        for (int i = 0; i < 4; i++) {
            int row = r + 16*i;
            float lo, hi; UNPK(lo, hi, acc[i][j]);
            og[jj*64 + row] = lo + hi + bj;
        }
    }
}

// conv: 8-wide tap from 10-float window
#define CT8(ROWP, W0m, W1m, W2m) { \
    const float* xr = (ROWP) + base; \
    float4 v0 = *(const float4*)xr; \
    float4 v1 = *(const float4*)(xr+4); \
    float2 v2 = *(const float2*)(xr+8); \
    float p[10] = {v0.x,v0.y,v0.z,v0.w, v1.x,v1.y,v1.z,v1.w, v2.x,v2.y}; \
    _Pragma("unroll") \
    for (int ii = 0; ii < 8; ii++) \
        a[ii] += (W0m)*p[ii] + (W1m)*p[ii+1] + (W2m)*p[ii+2]; }

// gemm phase: compute warps run GEMM, prefetch warps stage next weights
#define GPHASE(RELU, BM, IN, SIN, WCUR, BIAS, OUT, SO, NXT, WNXT) { \
    if (tid < 128) gemm48<RELU, BM>(IN, SIN, WCUR, BIAS, OUT, SO, tid); \
    else stage_w_half(NXT, WNXT, tid - 128); \
    __syncthreads(); }

// ---------------- main fused kernel: one CTA per batch element ----------------
// smem (floats): X 0(4352) | Y1a 4352(1088) | Y1b 5440(1088) | CB 6528(4352)
//                | T 10880(4352) | PF 15232(4352) | W0 19584(4352) | W1 23936(4352)
#define SMEM_FLOATS 28288

__global__ void __launch_bounds__(NT, 2)
esa_main_kernel(const float* __restrict__ x,
                const float* __restrict__ conv1_w, const float* __restrict__ conv1_b,
                const float* __restrict__ conv2_w, const float* __restrict__ conv2_b,
                const float* __restrict__ pm1_w,
                const float* __restrict__ pm2_w, const float* __restrict__ pm2_b,
                const float* __restrict__ mo_w,  const float* __restrict__ mo_b,
                const float* __restrict__ out_w, const float* __restrict__ out_b,
                const float* __restrict__ ln_g,  const float* __restrict__ ln_b,
                float* __restrict__ out)
{
    extern __shared__ float sm[];
    const int tid = threadIdx.x;
    const int b = blockIdx.x;
    float* X   = sm;
    float* Y1a = sm + 4352;
    float* Y1b = sm + 5440;
    float* CB  = sm + 6528;
    float* T   = sm + 10880;
    float* PF  = sm + 15232;
    float* W0  = sm + 19584;
    float* W1  = sm + 23936;

    // ---- load x + stage pm1 (cols 0..63 of 80-wide rows) into W0 ----
    {
        float4 pw[4]; pre_ld(pm1_w, 80, pw, tid);
        const float* xg = x + (size_t)b * 4096;
        for (int idx4 = tid; idx4 < 1024; idx4 += NT) {
            float4 v = __ldg((const float4*)xg + idx4);
            int c = idx4 >> 4, n = (idx4 & 15) << 2;
            float* rr = X + c*68 + 1 + n;
            rr[0] = v.x; rr[1] = v.y; rr[2] = v.z; rr[3] = v.w;
        }
        pre_st(W0, pw, tid);
        if (tid < 64) { X[tid*68] = 0.f; X[tid*68 + 65] = 0.f; }
        if (tid < 16) {
            Y1a[tid*68] = 0.f; Y1a[tid*68 + 65] = 0.f;
            Y1b[tid*68] = 0.f; Y1b[tid*68 + 65] = 0.f;
        }
    }
    __syncthreads();

    // ---- conv stack: two scales concurrently (half-CTA each), 8 outputs/thread ----
    {
        const int hh = tid >> 7;            // 0 or 1: which scale of the pair
        const int tl = tid & 127;
        const int o = tl >> 3, nq = tl & 7, base = nq * 8;
        float* Y1 = hh ? Y1b : Y1a;
        for (int s2 = 0; s2 < 2; s2++) {
            const int s = 2*s2 + hh;
            {   // conv1: 64 -> 16 channels
                const float* wr = conv1_w + s*3072 + o*192;
                float a[8];
                #pragma unroll
                for (int ii = 0; ii < 8; ii++) a[ii] = 0.f;
                #pragma unroll 4
                for (int c = 0; c < 64; c += 4) {
                    float4 wA = __ldg((const float4*)(wr + c*3));
                    float4 wB = __ldg((const float4*)(wr + c*3 + 4));
                    float4 wC = __ldg((const float4*)(wr + c*3 + 8));
                    CT8(X + (c+0)*68, wA.x, wA.y, wA.z);
                    CT8(X + (c+1)*68, wA.w, wB.x, wB.y);
                    CT8(X + (c+2)*68, wB.z, wB.w, wC.x);
                    CT8(X + (c+3)*68, wC.y, wC.z, wC.w);
                }
                float bb = __ldg(conv1_b + s*16 + o);
                float* yr = Y1 + o*68 + 1 + base;
                #pragma unroll
                for (int ii = 0; ii < 8; ii++) yr[ii] = fmaxf(a[ii] + bb, 0.f);
            }
            __syncthreads();
            {   // conv2: 16 -> 16 channels, transposed store into CB
                const float* wr = conv2_w + s*768 + o*48;
                float a[8];
                #pragma unroll
                for (int ii = 0; ii < 8; ii++) a[ii] = 0.f;
                #pragma unroll
                for (int c = 0; c < 16; c += 4) {
                    float4 wA = __ldg((const float4*)(wr + c*3));
                    float4 wB = __ldg((const float4*)(wr + c*3 + 4));
                    float4 wC = __ldg((const float4*)(wr + c*3 + 8));
                    CT8(Y1 + (c+0)*68, wA.x, wA.y, wA.z);
                    CT8(Y1 + (c+1)*68, wA.w, wB.x, wB.y);
                    CT8(Y1 + (c+2)*68, wB.z, wB.w, wC.x);
                    CT8(Y1 + (c+3)*68, wC.y, wC.z, wC.w);
                }
                float bb = __ldg(conv2_b + s*16 + o);
                int ch = s*16 + o;
                #pragma unroll
                for (int ii = 0; ii < 8; ii++)
                    CB[(base+ii)*68 + ch] = fmaxf(a[ii] + bb, 0.f);
            }
            __syncthreads();
        }
    }

    // ---- GEMM chain: compute warps (0-3) + prefetch warps (4-7) ----
    GPHASE(true,  true,  CB, 68, W0, g_p16,  T,  68, pm2_w, W1);  // pm1
    GPHASE(false, false, T,  68, W1, pm2_b,  PF, 68, g_wq,  W0);  // pm2
    GPHASE(false, false, PF, 68, W0, g_bq,   CB, 68, g_wk,  W1);  // Q
    GPHASE(false, false, PF, 68, W1, g_bk,   T,  68, g_wv,  W0);  // K
    GPHASE(false, false, PF, 68, W0, g_bv,   X,  68, mo_w,  W1);  // V

    // ---- attention: online softmax, one head per warp, 2 rows per lane ----
    // Each lane owns rows (lane, lane+32) at its head's column slice: in-place
    // CTX write into CB is race-free (disjoint cells, no barriers needed inside).
    {
        const int h8 = (tid >> 5) * 8;
        const int n0 = tid & 31;
        const float* q0p = CB + n0*68 + h8;
        const float* q1p = q0p + 32*68;
        ulonglong2 qa0 = *(const ulonglong2*)q0p;
        ulonglong2 qb0 = *(const ulonglong2*)(q0p + 4);
        ulonglong2 qa1 = *(const ulonglong2*)q1p;
        ulonglong2 qb1 = *(const ulonglong2*)(q1p + 4);
        float m0 = -3.0e38f, m1 = -3.0e38f, su0 = 0.f, su1 = 0.f;
        u64 c0[4] = {0ull,0ull,0ull,0ull};
        u64 c1[4] = {0ull,0ull,0ull,0ull};
        #pragma unroll 4
        for (int m = 0; m < 64; m++) {
            const float* kr = T + m*68 + h8;
            const float* vr = X + m*68 + h8;
            ulonglong2 ka = *(const ulonglong2*)kr;
            ulonglong2 kb = *(const ulonglong2*)(kr + 4);
            ulonglong2 va = *(const ulonglong2*)vr;
            ulonglong2 vb = *(const ulonglong2*)(vr + 4);
            u64 d0 = 0ull, d1 = 0ull;
            FMA2(d0, qa0.x, ka.x); FMA2(d0, qa0.y, ka.y);
            FMA2(d0, qb0.x, kb.x); FMA2(d0, qb0.y, kb.y);
            FMA2(d1, qa1.x, ka.x); FMA2(d1, qa1.y, ka.y);
            FMA2(d1, qb1.x, kb.x); FMA2(d1, qb1.y, kb.y);
            float lo, hi;
            UNPK(lo, hi, d0); float sv0 = lo + hi;
            UNPK(lo, hi, d1); float sv1 = lo + hi;
            float M0 = fmaxf(m0, sv0);
            float M1 = fmaxf(m1, sv1);
            float f0 = __expf(m0 - M0), e0 = __expf(sv0 - M0);
            float f1 = __expf(m1 - M1), e1 = __expf(sv1 - M1);
            m0 = M0; m1 = M1;
            su0 = su0*f0 + e0;
            su1 = su1*f1 + e1;
            u64 f0p, e0p, f1p, e1p;
            PK(f0p, f0, f0); PK(e0p, e0, e0);
            PK(f1p, f1, f1); PK(e1p, e1, e1);
            MUL2(c0[0], c0[0], f0p); FMA2(c0[0], e0p, va.x);
            MUL2(c0[1], c0[1], f0p); FMA2(c0[1], e0p, va.y);
            MUL2(c0[2], c0[2], f0p); FMA2(c0[2], e0p, vb.x);
            MUL2(c0[3], c0[3], f0p); FMA2(c0[3], e0p, vb.y);
            MUL2(c1[0], c1[0], f1p); FMA2(c1[0], e1p, va.x);
            MUL2(c1[1], c1[1], f1p); FMA2(c1[1], e1p, va.y);
            MUL2(c1[2], c1[2], f1p); FMA2(c1[2], e1p, vb.x);
            MUL2(c1[3], c1[3], f1p); FMA2(c1[3], e1p, vb.y);
        }
        float inv0 = 1.f / su0, inv1 = 1.f / su1;
        float w0l, w0h, w1l, w1h, w2l, w2h, w3l, w3h;
        UNPK(w0l,w0h,c0[0]); UNPK(w1l,w1h,c0[1]); UNPK(w2l,w2h,c0[2]); UNPK(w3l,w3h,c0[3]);
        float4 o1 = make_float4(w0l*inv0, w0h*inv0, w1l*inv0, w1h*inv0);
        float4 o2 = make_float4(w2l*inv0, w2h*inv0, w3l*inv0, w3h*inv0);
        *(float4*)(CB + n0*68 + h8)     = o1;
        *(float4*)(CB + n0*68 + h8 + 4) = o2;
        UNPK(w0l,w0h,c1[0]); UNPK(w1l,w1h,c1[1]); UNPK(w2l,w2h,c1[2]); UNPK(w3l,w3h,c1[3]);
        float4 o3 = make_float4(w0l*inv1, w0h*inv1, w1l*inv1, w1h*inv1);
        float4 o4 = make_float4(w2l*inv1, w2h*inv1, w3l*inv1, w3h*inv1);
        *(float4*)(CB + (n0+32)*68 + h8)     = o3;
        *(float4*)(CB + (n0+32)*68 + h8 + 4) = o4;
    }
    __syncthreads();

    // ---- mo (W1): CB -> T with +geo +residual; prefetch out_w -> W0 ----
    if (tid < 128) gemm_mo48(CB, W1, mo_b, PF, T, tid);
    else stage_w_half(out_w, W0, tid - 128);
    __syncthreads();

    // ---- LayerNorm over C (in place in T) ----
    {
        int n = tid >> 2, g = tid & 3;
        float* hr = T + n*68 + g*16;
        float4 v0 = *(const float4*)(hr);
        float4 v1 = *(const float4*)(hr + 4);
        float4 v2 = *(const float4*)(hr + 8);
        float4 v3 = *(const float4*)(hr + 12);
        float s  = v0.x+v0.y+v0.z+v0.w + v1.x+v1.y+v1.z+v1.w
                 + v2.x+v2.y+v2.z+v2.w + v3.x+v3.y+v3.z+v3.w;
        float s2 = v0.x*v0.x+v0.y*v0.y+v0.z*v0.z+v0.w*v0.w
                 + v1.x*v1.x+v1.y*v1.y+v1.z*v1.z+v1.w*v1.w
                 + v2.x*v2.x+v2.y*v2.y+v2.z*v2.z+v2.w*v2.w
                 + v3.x*v3.x+v3.y*v3.y+v3.z*v3.z+v3.w*v3.w;
        s  += __shfl_xor_sync(0xffffffffu, s, 1);
        s  += __shfl_xor_sync(0xffffffffu, s, 2);
        s2 += __shfl_xor_sync(0xffffffffu, s2, 1);
        s2 += __shfl_xor_sync(0xffffffffu, s2, 2);
        float mu  = s * 0.015625f;
        float var = s2 * 0.015625f - mu*mu;
        float r = rsqrtf(var + 1e-5f);
        int cb = g*16;
        float4 g0 = __ldg((const float4*)(ln_g + cb));
        float4 g1 = __ldg((const float4*)(ln_g + cb + 4));
        float4 g2 = __ldg((const float4*)(ln_g + cb + 8));
        float4 g3 = __ldg((const float4*)(ln_g + cb + 12));
        float4 b0 = __ldg((const float4*)(ln_b + cb));
        float4 b1 = __ldg((const float4*)(ln_b + cb + 4));
        float4 b2 = __ldg((const float4*)(ln_b + cb + 8));
        float4 b3 = __ldg((const float4*)(ln_b + cb + 12));
        hr[0]  = (v0.x-mu)*r*g0.x + b0.x;  hr[1]  = (v0.y-mu)*r*g0.y + b0.y;
        hr[2]  = (v0.z-mu)*r*g0.z + b0.z;  hr[3]  = (v0.w-mu)*r*g0.w + b0.w;
        hr[4]  = (v1.x-mu)*r*g1.x + b1.x;  hr[5]  = (v1.y-mu)*r*g1.y + b1.y;
        hr[6]  = (v1.z-mu)*r*g1.z + b1.z;  hr[7]  = (v1.w-mu)*r*g1.w + b1.w;
        hr[8]  = (v2.x-mu)*r*g2.x + b2.x;  hr[9]  = (v2.y-mu)*r*g2.y + b2.y;
        hr[10] = (v2.z-mu)*r*g2.z + b2.z;  hr[11] = (v2.w-mu)*r*g2.w + b2.w;
        hr[12] = (v3.x-mu)*r*g3.x + b3.x;  hr[13] = (v3.y-mu)*r*g3.y + b3.y;
        hr[14] = (v3.z-mu)*r*g3.z + b3.z;  hr[15] = (v3.w-mu)*r*g3.w + b3.w;
    }
    __syncthreads();

    // ---- final projection: straight to global, transposed layout ----
    if (tid < 128) gemm_out48(T, W0, out_b, out + (size_t)b * 4096, tid);
}

// ---------------- launch ----------------
extern "C" void kernel_launch(void* const* d_in, const int* in_sizes, int n_in,
                              void* d_out, int out_size)
{
    const float* x         = (const float*)d_in[0];
    const float* points    = (const float*)d_in[1];
    const float* conv1_w   = (const float*)d_in[2];
    const float* conv1_b   = (const float*)d_in[3];
    const float* conv2_w   = (const float*)d_in[4];
    const float* conv2_b   = (const float*)d_in[5];
    const float* pattern   = (const float*)d_in[6];
    const float* pm1_w     = (const float*)d_in[7];
    const float* pm1_b     = (const float*)d_in[8];
    const float* pm2_w     = (const float*)d_in[9];
    const float* pm2_b     = (const float*)d_in[10];
    const float* q_w       = (const float*)d_in[11];
    const float* q_b       = (const float*)d_in[12];
    const float* k_w       = (const float*)d_in[13];
    const float* k_b       = (const float*)d_in[14];
    const float* v_w       = (const float*)d_in[15];
    const float* v_b       = (const float*)d_in[16];
    const float* in_w      = (const float*)d_in[17];
    const float* in_b      = (const float*)d_in[18];
    const float* mo_w      = (const float*)d_in[19];
    const float* mo_b      = (const float*)d_in[20];
    const float* out_w     = (const float*)d_in[21];
    const float* out_b     = (const float*)d_in[22];
    const float* ln_g      = (const float*)d_in[23];
    const float* ln_b      = (const float*)d_in[24];
    const int*   adjacency = (const int*)d_in[25];

    int B = in_sizes[0] / 4096;
    size_t smem = SMEM_FLOATS * sizeof(float);
    cudaFuncSetAttribute(esa_main_kernel, cudaFuncAttributeMaxDynamicSharedMemorySize, (int)smem);

    esa_prep_kernel<<<24, NT>>>(points, adjacency, in_w, in_b, pattern, pm1_w, pm1_b,
                                q_w, q_b, k_w, k_b, v_w, v_b);
    esa_main_kernel<<<B, NT, smem>>>(x, conv1_w, conv1_b, conv2_w, conv2_b,
                                     pm1_w, pm2_w, pm2_b, mo_w, mo_b,
                                     out_w, out_b, ln_g, ln_b, (float*)d_out);
}

// round 10
// speedup vs baseline: 1.3312x; 1.2517x over previous
#include <cuda_runtime.h>
#include <math.h>

#define NT 256
typedef unsigned long long u64;

// f32x2 packed math (Blackwell)
#define FMA2(d,a,b)  asm("fma.rn.f32x2 %0, %1, %2, %0;" : "+l"(d) : "l"(a), "l"(b))
#define UNPK(lo,hi,p) asm("mov.b64 {%0,%1}, %2;" : "=f"(lo), "=f"(hi) : "l"(p))
#define PK(p,lo,hi)   asm("mov.b64 %0, {%1,%2};" : "=l"(p) : "f"(lo), "f"(hi))

// ---------------- device scratch ----------------
__device__ __align__(16) float g_geo[4096];
__device__ __align__(16) float g_p16[4096];
__device__ __align__(16) float g_wq[4096];
__device__ __align__(16) float g_wk[4096];
__device__ __align__(16) float g_wv[4096];
__device__ __align__(16) float g_bq[64];
__device__ __align__(16) float g_bk[64];
__device__ __align__(16) float g_bv[64];
__device__ __align__(16) float g_cw1t[12288];  // conv1 w: [s][c][t][o2*2+{lo:o2,hi:o2+8}]
__device__ __align__(16) float g_cw2t[3072];   // conv2 w: same layout, c<16

// ---------------- prep ----------------
__global__ void esa_prep_kernel(const float* __restrict__ points,
                                const int*   __restrict__ adjacency,
                                const float* __restrict__ in_w,
                                const float* __restrict__ in_b,
                                const float* __restrict__ pattern,
                                const float* __restrict__ pm1_w,
                                const float* __restrict__ pm1_b,
                                const float* __restrict__ conv1_w,
                                const float* __restrict__ conv2_w,
                                const float* __restrict__ q_w, const float* __restrict__ q_b,
                                const float* __restrict__ k_w, const float* __restrict__ k_b,
                                const float* __restrict__ v_w, const float* __restrict__ v_b)
{
    const int gtid = blockIdx.x * blockDim.x + threadIdx.x;
    const int gstride = gridDim.x * blockDim.x;
    const float scale = 0.3535533905932738f; // 1/sqrt(8)

    for (int idx = gtid; idx < 4096; idx += gstride) {
        int n = idx >> 6, m = idx & 63;
        float dx = points[n*3+0] - points[m*3+0];
        float dy = points[n*3+1] - points[m*3+1];
        float dz = points[n*3+2] - points[m*3+2];
        float dist = sqrtf(dx*dx + dy*dy + dz*dz + 1e-12f);
        g_geo[idx] = (adjacency[idx] > 0) ? 0.5f : (-0.1f / (1.0f + dist));
    }
    for (int idx = gtid; idx < 4096; idx += gstride) {
        int n = idx >> 6, j = idx & 63;
        float s = pm1_b[j];
        const float* wr = pm1_w + j*80 + 64;
        const float* pr = pattern + n*16;
        #pragma unroll
        for (int p = 0; p < 16; p++) s += pr[p] * wr[p];
        g_p16[idx] = s;
    }
    // transposed conv weights: contiguous over output-channel pairs
    for (int idx = gtid; idx < 12288; idx += gstride) {
        int s = idx / 3072, r = idx % 3072;
        int c = r / 48, r2 = r % 48;
        int t = r2 / 16, q = r2 % 16;
        int o = (q >> 1) + 8*(q & 1);
        g_cw1t[idx] = conv1_w[((s*16 + o)*64 + c)*3 + t];
    }
    for (int idx = gtid; idx < 3072; idx += gstride) {
        int s = idx / 768, r = idx % 768;
        int c = r / 48, r2 = r % 48;
        int t = r2 / 16, q = r2 % 16;
        int o = (q >> 1) + 8*(q & 1);
        g_cw2t[idx] = conv2_w[((s*16 + o)*16 + c)*3 + t];
    }
    for (int idx = gtid; idx < 3*4096; idx += gstride) {
        int which = idx >> 12;
        int o = (idx >> 6) & 63;
        int u = idx & 63;
        const float* wi = in_w + which*4096 + o*64;
        const float* wx = (which==0) ? q_w : (which==1) ? k_w : v_w;
        float s = 0.f;
        #pragma unroll 4
        for (int t = 0; t < 64; t++) s += wi[t] * wx[t*64 + u];
        if (which == 0) s *= scale;
        float* dst = (which==0) ? g_wq : (which==1) ? g_wk : g_wv;
        dst[o*64 + u] = s;
    }
    for (int idx = gtid; idx < 192; idx += gstride) {
        int which = idx >> 6, o = idx & 63;
        const float* wi = in_w + which*4096 + o*64;
        const float* bx = (which==0) ? q_b : (which==1) ? k_b : v_b;
        float s = in_b[which*64 + o];
        for (int t = 0; t < 64; t++) s += wi[t] * bx[t];
        if (which == 0) s *= scale;
        float* dst = (which==0) ? g_bq : (which==1) ? g_bk : g_bv;
        dst[o] = s;
    }
}

// ---------------- weight staging ----------------
__device__ __forceinline__ void pre_ld(const float* __restrict__ src, int sstr,
                                       float4* r, int tid) {
    #pragma unroll
    for (int i = 0; i < 4; i++) {
        int idx4 = tid + i*NT;
        int rr = idx4 >> 4, cc = (idx4 & 15) << 2;
        r[i] = __ldg((const float4*)(src + rr*sstr + cc));
    }
}
__device__ __forceinline__ void pre_st(float* __restrict__ Wd, const float4* r, int tid) {
    #pragma unroll
    for (int i = 0; i < 4; i++) {
        int idx4 = tid + i*NT;
        int rr = idx4 >> 4, cc = (idx4 & 15) << 2;
        *(float4*)(Wd + rr*68 + cc) = r[i];
    }
}
__device__ __forceinline__ void stage_w_half(const float* __restrict__ src,
                                             float* __restrict__ Wd, int t2) {
    float4 r[8];
    #pragma unroll
    for (int i = 0; i < 8; i++) {
        int idx4 = t2 + i*128;
        int rr = idx4 >> 4, cc = (idx4 & 15) << 2;
        r[i] = __ldg((const float4*)(src + rr*64 + cc));
    }
    #pragma unroll
    for (int i = 0; i < 8; i++) {
        int idx4 = t2 + i*128;
        int rr = idx4 >> 4, cc = (idx4 & 15) << 2;
        *(float4*)(Wd + rr*68 + cc) = r[i];
    }
}

// ---------------- f32x2 GEMM, 4x8 tiles on 128 threads ----------------
template<bool RELU, bool BIASMAT>
__device__ __forceinline__ void gemm48(const float* __restrict__ in, int sin,
                                       const float* __restrict__ W,
                                       const float* __restrict__ bias,
                                       float* __restrict__ outp, int so, int tid)
{
    const int r  = tid >> 3;
    const int j0 = tid & 7;
    u64 acc[4][8];
    #pragma unroll
    for (int i = 0; i < 4; i++)
        #pragma unroll
        for (int j = 0; j < 8; j++) acc[i][j] = 0ull;

    const float* ap = in + r*sin;
    const float* wp = W + j0*68;
    #pragma unroll 4
    for (int k = 0; k < 64; k += 4) {
        ulonglong2 a[4];
        a[0] = *(const ulonglong2*)(ap + k);
        a[1] = *(const ulonglong2*)(ap + 16*sin + k);
        a[2] = *(const ulonglong2*)(ap + 32*sin + k);
        a[3] = *(const ulonglong2*)(ap + 48*sin + k);
        #pragma unroll
        for (int j = 0; j < 8; j++) {
            ulonglong2 b = *(const ulonglong2*)(wp + j*8*68 + k);
            #pragma unroll
            for (int i = 0; i < 4; i++) {
                FMA2(acc[i][j], a[i].x, b.x);
                FMA2(acc[i][j], a[i].y, b.y);
            }
        }
    }
    #pragma unroll
    for (int j = 0; j < 8; j++) {
        int jj = j0 + 8*j;
        float bj = BIASMAT ? 0.f : __ldg(bias + jj);
        #pragma unroll
        for (int i = 0; i < 4; i++) {
            int row = r + 16*i;
            float lo, hi; UNPK(lo, hi, acc[i][j]);
            float v = lo + hi + bj;
            if (BIASMAT) v += __ldg(bias + row*64 + jj);
            if (RELU) v = fmaxf(v, 0.f);
            outp[row*so + jj] = v;
        }
    }
}

__device__ __forceinline__ void gemm_mo48(const float* __restrict__ in,
                                          const float* __restrict__ W,
                                          const float* __restrict__ mo_b,
                                          const float* __restrict__ pf,
                                          float* __restrict__ outp, int tid)
{
    const int r  = tid >> 3;
    const int j0 = tid & 7;
    u64 acc[4][8];
    #pragma unroll
    for (int i = 0; i < 4; i++)
        #pragma unroll
        for (int j = 0; j < 8; j++) acc[i][j] = 0ull;

    const float* ap = in + r*68;
    const float* wp = W + j0*68;
    #pragma unroll 4
    for (int k = 0; k < 64; k += 4) {
        ulonglong2 a[4];
        a[0] = *(const ulonglong2*)(ap + k);
        a[1] = *(const ulonglong2*)(ap + 16*68 + k);
        a[2] = *(const ulonglong2*)(ap + 32*68 + k);
        a[3] = *(const ulonglong2*)(ap + 48*68 + k);
        #pragma unroll
        for (int j = 0; j < 8; j++) {
            ulonglong2 b = *(const ulonglong2*)(wp + j*8*68 + k);
            #pragma unroll
            for (int i = 0; i < 4; i++) {
                FMA2(acc[i][j], a[i].x, b.x);
                FMA2(acc[i][j], a[i].y, b.y);
            }
        }
    }
    #pragma unroll
    for (int j = 0; j < 8; j++) {
        int jj = j0 + 8*j;
        float bj = __ldg(mo_b + jj);
        #pragma unroll
        for (int i = 0; i < 4; i++) {
            int row = r + 16*i;
            float lo, hi; UNPK(lo, hi, acc[i][j]);
            outp[row*68 + jj] = lo + hi + bj + __ldg(g_geo + row*64 + jj) + pf[row*68 + jj];
        }
    }
}

__device__ __forceinline__ void gemm_out48(const float* __restrict__ in,
                                           const float* __restrict__ W,
                                           const float* __restrict__ bias,
                                           float* __restrict__ og, int tid)
{
    const int r  = tid >> 3;
    const int j0 = tid & 7;
    u64 acc[4][8];
    #pragma unroll
    for (int i = 0; i < 4; i++)
        #pragma unroll
        for (int j = 0; j < 8; j++) acc[i][j] = 0ull;

    const float* ap = in + r*68;
    const float* wp = W + j0*68;
    #pragma unroll 4
    for (int k = 0; k < 64; k += 4) {
        ulonglong2 a[4];
        a[0] = *(const ulonglong2*)(ap + k);
        a[1] = *(const ulonglong2*)(ap + 16*68 + k);
        a[2] = *(const ulonglong2*)(ap + 32*68 + k);
        a[3] = *(const ulonglong2*)(ap + 48*68 + k);
        #pragma unroll
        for (int j = 0; j < 8; j++) {
            ulonglong2 b = *(const ulonglong2*)(wp + j*8*68 + k);
            #pragma unroll
            for (int i = 0; i < 4; i++) {
                FMA2(acc[i][j], a[i].x, b.x);
                FMA2(acc[i][j], a[i].y, b.y);
            }
        }
    }
    #pragma unroll
    for (int j = 0; j < 8; j++) {
        int jj = j0 + 8*j;
        float bj = __ldg(bias + jj);
        #pragma unroll
        for (int i = 0; i < 4; i++) {
            int row = r + 16*i;
            float lo, hi; UNPK(lo, hi, acc[i][j]);
            og[jj*64 + row] = lo + hi + bj;
        }
    }
}

// FMA2 conv micro-step: 2 output channels x 4 output pairs for one input channel
#define CONV_STEP(SRCROW, WT, CIDX) { \
    const float* xr = (SRCROW); \
    float4 v0 = *(const float4*)xr; \
    float4 v1 = *(const float4*)(xr+4); \
    float2 v2 = *(const float2*)(xr+8); \
    u64 e0,e1,e2,e3,e4,d0,d1,d2,d3; \
    PK(e0,v0.x,v0.y); PK(e1,v0.z,v0.w); PK(e2,v1.x,v1.y); PK(e3,v1.z,v1.w); PK(e4,v2.x,v2.y); \
    PK(d0,v0.y,v0.z); PK(d1,v0.w,v1.x); PK(d2,v1.y,v1.z); PK(d3,v1.w,v2.x); \
    float2 wA = __ldg((const float2*)((WT) + ((CIDX)*3+0)*16)); \
    float2 wB = __ldg((const float2*)((WT) + ((CIDX)*3+1)*16)); \
    float2 wC = __ldg((const float2*)((WT) + ((CIDX)*3+2)*16)); \
    u64 w00,w01,w10,w11,w20,w21; \
    PK(w00,wA.x,wA.x); PK(w01,wA.y,wA.y); \
    PK(w10,wB.x,wB.x); PK(w11,wB.y,wB.y); \
    PK(w20,wC.x,wC.x); PK(w21,wC.y,wC.y); \
    FMA2(a0[0],w00,e0); FMA2(a0[0],w10,d0); FMA2(a0[0],w20,e1); \
    FMA2(a0[1],w00,e1); FMA2(a0[1],w10,d1); FMA2(a0[1],w20,e2); \
    FMA2(a0[2],w00,e2); FMA2(a0[2],w10,d2); FMA2(a0[2],w20,e3); \
    FMA2(a0[3],w00,e3); FMA2(a0[3],w10,d3); FMA2(a0[3],w20,e4); \
    FMA2(a1[0],w01,e0); FMA2(a1[0],w11,d0); FMA2(a1[0],w21,e1); \
    FMA2(a1[1],w01,e1); FMA2(a1[1],w11,d1); FMA2(a1[1],w21,e2); \
    FMA2(a1[2],w01,e2); FMA2(a1[2],w11,d2); FMA2(a1[2],w21,e3); \
    FMA2(a1[3],w01,e3); FMA2(a1[3],w11,d3); FMA2(a1[3],w21,e4); }

// gemm phase: compute warps run GEMM, prefetch warps stage next weights
#define GPHASE(RELU, BM, IN, SIN, WCUR, BIAS, OUT, SO, NXT, WNXT) { \
    if (tid < 128) gemm48<RELU, BM>(IN, SIN, WCUR, BIAS, OUT, SO, tid); \
    else stage_w_half(NXT, WNXT, tid - 128); \
    __syncthreads(); }

// ---------------- main fused kernel: one CTA per batch element ----------------
// smem (floats): X 0(4352) | CB 4352(4352) | T 8704(4352) | PF 13056(4352)
//                | W0 17408(4352) | W1 21760(4352; aliased as 4x Y1 during conv)
#define SMEM_FLOATS 26112

__global__ void __launch_bounds__(NT, 2)
esa_main_kernel(const float* __restrict__ x,
                const float* __restrict__ conv1_b, const float* __restrict__ conv2_b,
                const float* __restrict__ pm1_w,
                const float* __restrict__ pm2_w, const float* __restrict__ pm2_b,
                const float* __restrict__ mo_w,  const float* __restrict__ mo_b,
                const float* __restrict__ out_w, const float* __restrict__ out_b,
                const float* __restrict__ ln_g,  const float* __restrict__ ln_b,
                float* __restrict__ out)
{
    extern __shared__ float sm[];
    const int tid = threadIdx.x;
    const int b = blockIdx.x;
    float* X  = sm;
    float* CB = sm + 4352;
    float* T  = sm + 8704;
    float* PF = sm + 13056;
    float* W0 = sm + 17408;
    float* W1 = sm + 21760;

    // ---- load x + stage pm1 (cols 0..63 of 80-wide rows) into W0 ----
    {
        float4 pw[4]; pre_ld(pm1_w, 80, pw, tid);
        const float* xg = x + (size_t)b * 4096;
        for (int idx4 = tid; idx4 < 1024; idx4 += NT) {
            float4 v = __ldg((const float4*)xg + idx4);
            int c = idx4 >> 4, n = (idx4 & 15) << 2;
            float* rr = X + c*68 + 1 + n;
            rr[0] = v.x; rr[1] = v.y; rr[2] = v.z; rr[3] = v.w;
        }
        pre_st(W0, pw, tid);
        if (tid < 64) {
            X[tid*68] = 0.f;  X[tid*68 + 65] = 0.f;    // x pads
            W1[tid*68] = 0.f; W1[tid*68 + 65] = 0.f;   // Y1 pads (4 scales x 16 rows)
        }
    }
    __syncthreads();

    // ---- conv stack: 4 scales in one pass; thread = (s, o2, nq), 2 out-ch each ----
    {
        const int s  = tid >> 6;
        const int o2 = (tid >> 3) & 7;
        const int nq = tid & 7;
        const int base = nq * 8;
        float* Y1 = W1 + s*1088;
        {   // conv1: 64 -> 16 channels
            const float* wt = g_cw1t + s*3072 + o2*2;
            u64 a0[4], a1[4];
            #pragma unroll
            for (int j = 0; j < 4; j++) { a0[j]=0ull; a1[j]=0ull; }
            #pragma unroll 2
            for (int c = 0; c < 64; c++)
                CONV_STEP(X + c*68 + base, wt, c);
            float bb0 = __ldg(conv1_b + s*16 + o2);
            float bb1 = __ldg(conv1_b + s*16 + o2 + 8);
            float* y0 = Y1 + o2*68 + 1 + base;
            float* y1r = Y1 + (o2+8)*68 + 1 + base;
            #pragma unroll
            for (int j = 0; j < 4; j++) {
                float lo, hi;
                UNPK(lo, hi, a0[j]);
                y0[2*j] = fmaxf(lo+bb0, 0.f); y0[2*j+1] = fmaxf(hi+bb0, 0.f);
                UNPK(lo, hi, a1[j]);
                y1r[2*j] = fmaxf(lo+bb1, 0.f); y1r[2*j+1] = fmaxf(hi+bb1, 0.f);
            }
        }
        __syncthreads();
        {   // conv2: 16 -> 16 channels, transposed store into CB
            const float* wt = g_cw2t + s*768 + o2*2;
            u64 a0[4], a1[4];
            #pragma unroll
            for (int j = 0; j < 4; j++) { a0[j]=0ull; a1[j]=0ull; }
            #pragma unroll 2
            for (int c = 0; c < 16; c++)
                CONV_STEP(Y1 + c*68 + base, wt, c);
            float bb0 = __ldg(conv2_b + s*16 + o2);
            float bb1 = __ldg(conv2_b + s*16 + o2 + 8);
            int ch0 = s*16 + o2, ch1 = ch0 + 8;
            #pragma unroll
            for (int j = 0; j < 4; j++) {
                float lo, hi;
                UNPK(lo, hi, a0[j]);
                CB[(base+2*j)*68 + ch0]   = fmaxf(lo+bb0, 0.f);
                CB[(base+2*j+1)*68 + ch0] = fmaxf(hi+bb0, 0.f);
                UNPK(lo, hi, a1[j]);
                CB[(base+2*j)*68 + ch1]   = fmaxf(lo+bb1, 0.f);
                CB[(base+2*j+1)*68 + ch1] = fmaxf(hi+bb1, 0.f);
            }
        }
        __syncthreads();
    }

    // ---- GEMM chain: compute warps (0-3) + prefetch warps (4-7) ----
    GPHASE(true,  true,  CB, 68, W0, g_p16,  T,  68, pm2_w, W1);  // pm1
    GPHASE(false, false, T,  68, W1, pm2_b,  PF, 68, g_wq,  W0);  // pm2
    GPHASE(false, false, PF, 68, W0, g_bq,   CB, 68, g_wk,  W1);  // Q
    GPHASE(false, false, PF, 68, W1, g_bk,   T,  68, g_wv,  W0);  // K
    GPHASE(false, false, PF, 68, W0, g_bv,   X,  68, mo_w,  W1);  // V

    // ---- attention: single pass, no max-sub (scores are small), 2 rows/lane ----
    {
        const int h8 = (tid >> 5) * 8;
        const int n0 = tid & 31;
        const float* q0p = CB + n0*68 + h8;
        const float* q1p = q0p + 32*68;
        ulonglong2 qa0 = *(const ulonglong2*)q0p;
        ulonglong2 qb0 = *(const ulonglong2*)(q0p + 4);
        ulonglong2 qa1 = *(const ulonglong2*)q1p;
        ulonglong2 qb1 = *(const ulonglong2*)(q1p + 4);
        float su0 = 0.f, su1 = 0.f;
        u64 c0[4] = {0ull,0ull,0ull,0ull};
        u64 c1[4] = {0ull,0ull,0ull,0ull};
        #pragma unroll 4
        for (int m = 0; m < 64; m++) {
            const float* kr = T + m*68 + h8;
            const float* vr = X + m*68 + h8;
            ulonglong2 ka = *(const ulonglong2*)kr;
            ulonglong2 kb = *(const ulonglong2*)(kr + 4);
            ulonglong2 va = *(const ulonglong2*)vr;
            ulonglong2 vb = *(const ulonglong2*)(vr + 4);
            u64 d0 = 0ull, d1 = 0ull;
            FMA2(d0, qa0.x, ka.x); FMA2(d0, qa0.y, ka.y);
            FMA2(d0, qb0.x, kb.x); FMA2(d0, qb0.y, kb.y);
            FMA2(d1, qa1.x, ka.x); FMA2(d1, qa1.y, ka.y);
            FMA2(d1, qb1.x, kb.x); FMA2(d1, qb1.y, kb.y);
            float lo, hi;
            UNPK(lo, hi, d0); float e0 = __expf(lo + hi);
            UNPK(lo, hi, d1); float e1 = __expf(lo + hi);
            su0 += e0; su1 += e1;
            u64 e0p, e1p;
            PK(e0p, e0, e0); PK(e1p, e1, e1);
            FMA2(c0[0], e0p, va.x); FMA2(c0[1], e0p, va.y);
            FMA2(c0[2], e0p, vb.x); FMA2(c0[3], e0p, vb.y);
            FMA2(c1[0], e1p, va.x); FMA2(c1[1], e1p, va.y);
            FMA2(c1[2], e1p, vb.x); FMA2(c1[3], e1p, vb.y);
        }
        float inv0 = 1.f / su0, inv1 = 1.f / su1;
        float w0l,w0h,w1l,w1h,w2l,w2h,w3l,w3h;
        UNPK(w0l,w0h,c0[0]); UNPK(w1l,w1h,c0[1]); UNPK(w2l,w2h,c0[2]); UNPK(w3l,w3h,c0[3]);
        *(float4*)(CB + n0*68 + h8)     = make_float4(w0l*inv0, w0h*inv0, w1l*inv0, w1h*inv0);
        *(float4*)(CB + n0*68 + h8 + 4) = make_float4(w2l*inv0, w2h*inv0, w3l*inv0, w3h*inv0);
        UNPK(w0l,w0h,c1[0]); UNPK(w1l,w1h,c1[1]); UNPK(w2l,w2h,c1[2]); UNPK(w3l,w3h,c1[3]);
        *(float4*)(CB + (n0+32)*68 + h8)     = make_float4(w0l*inv1, w0h*inv1, w1l*inv1, w1h*inv1);
        *(float4*)(CB + (n0+32)*68 + h8 + 4) = make_float4(w2l*inv1, w2h*inv1, w3l*inv1, w3h*inv1);
    }
    __syncthreads();

    // ---- mo (W1): CB -> T with +geo +residual; prefetch out_w -> W0 ----
    if (tid < 128) gemm_mo48(CB, W1, mo_b, PF, T, tid);
    else stage_w_half(out_w, W0, tid - 128);
    __syncthreads();

    // ---- LayerNorm over C (in place in T) ----
    {
        int n = tid >> 2, g = tid & 3;
        float* hr = T + n*68 + g*16;
        float4 v0 = *(const float4*)(hr);
        float4 v1 = *(const float4*)(hr + 4);
        float4 v2 = *(const float4*)(hr + 8);
        float4 v3 = *(const float4*)(hr + 12);
        float s  = v0.x+v0.y+v0.z+v0.w + v1.x+v1.y+v1.z+v1.w
                 + v2.x+v2.y+v2.z+v2.w + v3.x+v3.y+v3.z+v3.w;
        float s2 = v0.x*v0.x+v0.y*v0.y+v0.z*v0.z+v0.w*v0.w
                 + v1.x*v1.x+v1.y*v1.y+v1.z*v1.z+v1.w*v1.w
                 + v2.x*v2.x+v2.y*v2.y+v2.z*v2.z+v2.w*v2.w
                 + v3.x*v3.x+v3.y*v3.y+v3.z*v3.z+v3.w*v3.w;
        s  += __shfl_xor_sync(0xffffffffu, s, 1);
        s  += __shfl_xor_sync(0xffffffffu, s, 2);
        s2 += __shfl_xor_sync(0xffffffffu, s2, 1);
        s2 += __shfl_xor_sync(0xffffffffu, s2, 2);
        float mu  = s * 0.015625f;
        float var = s2 * 0.015625f - mu*mu;
        float r = rsqrtf(var + 1e-5f);
        int cb = g*16;
        float4 g0 = __ldg((const float4*)(ln_g + cb));
        float4 g1 = __ldg((const float4*)(ln_g + cb + 4));
        float4 g2 = __ldg((const float4*)(ln_g + cb + 8));
        float4 g3 = __ldg((const float4*)(ln_g + cb + 12));
        float4 b0 = __ldg((const float4*)(ln_b + cb));
        float4 b1 = __ldg((const float4*)(ln_b + cb + 4));
        float4 b2 = __ldg((const float4*)(ln_b + cb + 8));
        float4 b3 = __ldg((const float4*)(ln_b + cb + 12));
        hr[0]  = (v0.x-mu)*r*g0.x + b0.x;  hr[1]  = (v0.y-mu)*r*g0.y + b0.y;
        hr[2]  = (v0.z-mu)*r*g0.z + b0.z;  hr[3]  = (v0.w-mu)*r*g0.w + b0.w;
        hr[4]  = (v1.x-mu)*r*g1.x + b1.x;  hr[5]  = (v1.y-mu)*r*g1.y + b1.y;
        hr[6]  = (v1.z-mu)*r*g1.z + b1.z;  hr[7]  = (v1.w-mu)*r*g1.w + b1.w;
        hr[8]  = (v2.x-mu)*r*g2.x + b2.x;  hr[9]  = (v2.y-mu)*r*g2.y + b2.y;
        hr[10] = (v2.z-mu)*r*g2.z + b2.z;  hr[11] = (v2.w-mu)*r*g2.w + b2.w;
        hr[12] = (v3.x-mu)*r*g3.x + b3.x;  hr[13] = (v3.y-mu)*r*g3.y + b3.y;
        hr[14] = (v3.z-mu)*r*g3.z + b3.z;  hr[15] = (v3.w-mu)*r*g3.w + b3.w;
    }
    __syncthreads();

    // ---- final projection: straight to global, transposed layout ----
    if (tid < 128) gemm_out48(T, W0, out_b, out + (size_t)b * 4096, tid);
}

// ---------------- launch ----------------
extern "C" void kernel_launch(void* const* d_in, const int* in_sizes, int n_in,
                              void* d_out, int out_size)
{
    const float* x         = (const float*)d_in[0];
    const float* points    = (const float*)d_in[1];
    const float* conv1_w   = (const float*)d_in[2];
    const float* conv1_b   = (const float*)d_in[3];
    const float* conv2_w   = (const float*)d_in[4];
    const float* conv2_b   = (const float*)d_in[5];
    const float* pattern   = (const float*)d_in[6];
    const float* pm1_w     = (const float*)d_in[7];
    const float* pm1_b     = (const float*)d_in[8];
    const float* pm2_w     = (const float*)d_in[9];
    const float* pm2_b     = (const float*)d_in[10];
    const float* q_w       = (const float*)d_in[11];
    const float* q_b       = (const float*)d_in[12];
    const float* k_w       = (const float*)d_in[13];
    const float* k_b       = (const float*)d_in[14];
    const float* v_w       = (const float*)d_in[15];
    const float* v_b       = (const float*)d_in[16];
    const float* in_w      = (const float*)d_in[17];
    const float* in_b      = (const float*)d_in[18];
    const float* mo_w      = (const float*)d_in[19];
    const float* mo_b      = (const float*)d_in[20];
    const float* out_w     = (const float*)d_in[21];
    const float* out_b     = (const float*)d_in[22];
    const float* ln_g      = (const float*)d_in[23];
    const float* ln_b      = (const float*)d_in[24];
    const int*   adjacency = (const int*)d_in[25];

    int B = in_sizes[0] / 4096;
    size_t smem = SMEM_FLOATS * sizeof(float);
    cudaFuncSetAttribute(esa_main_kernel, cudaFuncAttributeMaxDynamicSharedMemorySize, (int)smem);

    esa_prep_kernel<<<24, NT>>>(points, adjacency, in_w, in_b, pattern, pm1_w, pm1_b,
                                conv1_w, conv2_w,
                                q_w, q_b, k_w, k_b, v_w, v_b);
    esa_main_kernel<<<B, NT, smem>>>(x, conv1_b, conv2_b,
                                     pm1_w, pm2_w, pm2_b, mo_w, mo_b,
                                     out_w, out_b, ln_g, ln_b, (float*)d_out);
}

// round 11
// speedup vs baseline: 1.3432x; 1.0091x over previous
#include <cuda_runtime.h>
#include <math.h>

#define NT 256
typedef unsigned long long u64;

// f32x2 packed math (Blackwell)
#define FMA2(d,a,b)  asm("fma.rn.f32x2 %0, %1, %2, %0;" : "+l"(d) : "l"(a), "l"(b))
#define UNPK(lo,hi,p) asm("mov.b64 {%0,%1}, %2;" : "=f"(lo), "=f"(hi) : "l"(p))
#define PK(p,lo,hi)   asm("mov.b64 %0, {%1,%2};" : "=l"(p) : "f"(lo), "f"(hi))

// ---------------- device scratch ----------------
__device__ __align__(16) float g_geo[4096];
__device__ __align__(16) float g_p16[4096];
__device__ __align__(16) float g_wq[4096];
__device__ __align__(16) float g_wk[4096];
__device__ __align__(16) float g_wv[4096];
__device__ __align__(16) float g_bq[64];
__device__ __align__(16) float g_bk[64];
__device__ __align__(16) float g_bv[64];
// conv weights, channel-pair records: [s][c2][o2][16]
//   j 0..5 : channel 2*c2   : (t0:lo,hi)(t1:lo,hi)(t2:lo,hi), lo=o2, hi=o2+8
//   j 6..11: channel 2*c2+1 : same
__device__ __align__(16) float g_cw1p[16384];
__device__ __align__(16) float g_cw2p[4096];

// ---------------- prep ----------------
__global__ void esa_prep_kernel(const float* __restrict__ points,
                                const int*   __restrict__ adjacency,
                                const float* __restrict__ in_w,
                                const float* __restrict__ in_b,
                                const float* __restrict__ pattern,
                                const float* __restrict__ pm1_w,
                                const float* __restrict__ pm1_b,
                                const float* __restrict__ conv1_w,
                                const float* __restrict__ conv2_w,
                                const float* __restrict__ q_w, const float* __restrict__ q_b,
                                const float* __restrict__ k_w, const float* __restrict__ k_b,
                                const float* __restrict__ v_w, const float* __restrict__ v_b)
{
    const int gtid = blockIdx.x * blockDim.x + threadIdx.x;
    const int gstride = gridDim.x * blockDim.x;
    const float scale = 0.3535533905932738f; // 1/sqrt(8)

    for (int idx = gtid; idx < 4096; idx += gstride) {
        int n = idx >> 6, m = idx & 63;
        float dx = points[n*3+0] - points[m*3+0];
        float dy = points[n*3+1] - points[m*3+1];
        float dz = points[n*3+2] - points[m*3+2];
        float dist = sqrtf(dx*dx + dy*dy + dz*dz + 1e-12f);
        g_geo[idx] = (adjacency[idx] > 0) ? 0.5f : (-0.1f / (1.0f + dist));
    }
    for (int idx = gtid; idx < 4096; idx += gstride) {
        int n = idx >> 6, j = idx & 63;
        float s = pm1_b[j];
        const float* wr = pm1_w + j*80 + 64;
        const float* pr = pattern + n*16;
        #pragma unroll
        for (int p = 0; p < 16; p++) s += pr[p] * wr[p];
        g_p16[idx] = s;
    }
    // conv weight pair records
    for (int idx = gtid; idx < 16384; idx += gstride) {
        int j  = idx & 15;
        int o2 = (idx >> 4) & 7;
        int c2 = (idx >> 7) & 31;
        int s  = idx >> 12;
        float v = 0.f;
        if (j < 12) {
            int half = j / 6, jj = j % 6;
            int t = jj >> 1, hb = jj & 1;
            int c = 2*c2 + half;
            int o = o2 + 8*hb;
            v = conv1_w[((s*16 + o)*64 + c)*3 + t];
        }
        g_cw1p[idx] = v;
    }
    for (int idx = gtid; idx < 4096; idx += gstride) {
        int j  = idx & 15;
        int o2 = (idx >> 4) & 7;
        int c2 = (idx >> 7) & 7;
        int s  = idx >> 10;
        float v = 0.f;
        if (j < 12) {
            int half = j / 6, jj = j % 6;
            int t = jj >> 1, hb = jj & 1;
            int c = 2*c2 + half;
            int o = o2 + 8*hb;
            v = conv2_w[((s*16 + o)*16 + c)*3 + t];
        }
        g_cw2p[idx] = v;
    }
    for (int idx = gtid; idx < 3*4096; idx += gstride) {
        int which = idx >> 12;
        int o = (idx >> 6) & 63;
        int u = idx & 63;
        const float* wi = in_w + which*4096 + o*64;
        const float* wx = (which==0) ? q_w : (which==1) ? k_w : v_w;
        float s = 0.f;
        #pragma unroll 4
        for (int t = 0; t < 64; t++) s += wi[t] * wx[t*64 + u];
        if (which == 0) s *= scale;
        float* dst = (which==0) ? g_wq : (which==1) ? g_wk : g_wv;
        dst[o*64 + u] = s;
    }
    for (int idx = gtid; idx < 192; idx += gstride) {
        int which = idx >> 6, o = idx & 63;
        const float* wi = in_w + which*4096 + o*64;
        const float* bx = (which==0) ? q_b : (which==1) ? k_b : v_b;
        float s = in_b[which*64 + o];
        for (int t = 0; t < 64; t++) s += wi[t] * bx[t];
        if (which == 0) s *= scale;
        float* dst = (which==0) ? g_bq : (which==1) ? g_bk : g_bv;
        dst[o] = s;
    }
}

// ---------------- weight staging ----------------
__device__ __forceinline__ void pre_ld(const float* __restrict__ src, int sstr,
                                       float4* r, int tid) {
    #pragma unroll
    for (int i = 0; i < 4; i++) {
        int idx4 = tid + i*NT;
        int rr = idx4 >> 4, cc = (idx4 & 15) << 2;
        r[i] = __ldg((const float4*)(src + rr*sstr + cc));
    }
}
__device__ __forceinline__ void pre_st(float* __restrict__ Wd, const float4* r, int tid) {
    #pragma unroll
    for (int i = 0; i < 4; i++) {
        int idx4 = tid + i*NT;
        int rr = idx4 >> 4, cc = (idx4 & 15) << 2;
        *(float4*)(Wd + rr*68 + cc) = r[i];
    }
}
__device__ __forceinline__ void stage_w_half(const float* __restrict__ src,
                                             float* __restrict__ Wd, int t2) {
    float4 r[8];
    #pragma unroll
    for (int i = 0; i < 8; i++) {
        int idx4 = t2 + i*128;
        int rr = idx4 >> 4, cc = (idx4 & 15) << 2;
        r[i] = __ldg((const float4*)(src + rr*64 + cc));
    }
    #pragma unroll
    for (int i = 0; i < 8; i++) {
        int idx4 = t2 + i*128;
        int rr = idx4 >> 4, cc = (idx4 & 15) << 2;
        *(float4*)(Wd + rr*68 + cc) = r[i];
    }
}

// ---------------- f32x2 GEMM, 4x8 tiles on 128 threads ----------------
template<bool RELU, bool BIASMAT>
__device__ __forceinline__ void gemm48(const float* __restrict__ in, int sin,
                                       const float* __restrict__ W,
                                       const float* __restrict__ bias,
                                       float* __restrict__ outp, int so, int tid)
{
    const int r  = tid >> 3;
    const int j0 = tid & 7;
    u64 acc[4][8];
    #pragma unroll
    for (int i = 0; i < 4; i++)
        #pragma unroll
        for (int j = 0; j < 8; j++) acc[i][j] = 0ull;

    const float* ap = in + r*sin;
    const float* wp = W + j0*68;
    #pragma unroll 4
    for (int k = 0; k < 64; k += 4) {
        ulonglong2 a[4];
        a[0] = *(const ulonglong2*)(ap + k);
        a[1] = *(const ulonglong2*)(ap + 16*sin + k);
        a[2] = *(const ulonglong2*)(ap + 32*sin + k);
        a[3] = *(const ulonglong2*)(ap + 48*sin + k);
        #pragma unroll
        for (int j = 0; j < 8; j++) {
            ulonglong2 b = *(const ulonglong2*)(wp + j*8*68 + k);
            #pragma unroll
            for (int i = 0; i < 4; i++) {
                FMA2(acc[i][j], a[i].x, b.x);
                FMA2(acc[i][j], a[i].y, b.y);
            }
        }
    }
    #pragma unroll
    for (int j = 0; j < 8; j++) {
        int jj = j0 + 8*j;
        float bj = BIASMAT ? 0.f : __ldg(bias + jj);
        #pragma unroll
        for (int i = 0; i < 4; i++) {
            int row = r + 16*i;
            float lo, hi; UNPK(lo, hi, acc[i][j]);
            float v = lo + hi + bj;
            if (BIASMAT) v += __ldg(bias + row*64 + jj);
            if (RELU) v = fmaxf(v, 0.f);
            outp[row*so + jj] = v;
        }
    }
}

// mo projection + geo + residual + FUSED LayerNorm (row = 8 consecutive lanes)
__device__ __forceinline__ void gemm_mo_ln48(const float* __restrict__ in,
                                             const float* __restrict__ W,
                                             const float* __restrict__ mo_b,
                                             const float* __restrict__ pf,
                                             const float* __restrict__ LNS,
                                             float* __restrict__ outp, int tid)
{
    const int r  = tid >> 3;
    const int j0 = tid & 7;
    u64 acc[4][8];
    #pragma unroll
    for (int i = 0; i < 4; i++)
        #pragma unroll
        for (int j = 0; j < 8; j++) acc[i][j] = 0ull;

    const float* ap = in + r*68;
    const float* wp = W + j0*68;
    #pragma unroll 4
    for (int k = 0; k < 64; k += 4) {
        ulonglong2 a[4];
        a[0] = *(const ulonglong2*)(ap + k);
        a[1] = *(const ulonglong2*)(ap + 16*68 + k);
        a[2] = *(const ulonglong2*)(ap + 32*68 + k);
        a[3] = *(const ulonglong2*)(ap + 48*68 + k);
        #pragma unroll
        for (int j = 0; j < 8; j++) {
            ulonglong2 b = *(const ulonglong2*)(wp + j*8*68 + k);
            #pragma unroll
            for (int i = 0; i < 4; i++) {
                FMA2(acc[i][j], a[i].x, b.x);
                FMA2(acc[i][j], a[i].y, b.y);
            }
        }
    }
    #pragma unroll
    for (int i = 0; i < 4; i++) {
        int row = r + 16*i;
        float v[8];
        float rs = 0.f, rq = 0.f;
        #pragma unroll
        for (int j = 0; j < 8; j++) {
            int jj = j0 + 8*j;
            float lo, hi; UNPK(lo, hi, acc[i][j]);
            float t = lo + hi + __ldg(mo_b + jj) + __ldg(g_geo + row*64 + jj)
                    + pf[row*68 + jj];
            v[j] = t; rs += t; rq += t*t;
        }
        rs += __shfl_xor_sync(0xffffffffu, rs, 1);
        rq += __shfl_xor_sync(0xffffffffu, rq, 1);
        rs += __shfl_xor_sync(0xffffffffu, rs, 2);
        rq += __shfl_xor_sync(0xffffffffu, rq, 2);
        rs += __shfl_xor_sync(0xffffffffu, rs, 4);
        rq += __shfl_xor_sync(0xffffffffu, rq, 4);
        float mu  = rs * 0.015625f;
        float var = rq * 0.015625f - mu*mu;
        float ri = rsqrtf(var + 1e-5f);
        #pragma unroll
        for (int j = 0; j < 8; j++) {
            int jj = j0 + 8*j;
            outp[row*68 + jj] = (v[j] - mu) * ri * LNS[jj] + LNS[64 + jj];
        }
    }
}

__device__ __forceinline__ void gemm_out48(const float* __restrict__ in,
                                           const float* __restrict__ W,
                                           const float* __restrict__ bias,
                                           float* __restrict__ og, int tid)
{
    const int r  = tid >> 3;
    const int j0 = tid & 7;
    u64 acc[4][8];
    #pragma unroll
    for (int i = 0; i < 4; i++)
        #pragma unroll
        for (int j = 0; j < 8; j++) acc[i][j] = 0ull;

    const float* ap = in + r*68;
    const float* wp = W + j0*68;
    #pragma unroll 4
    for (int k = 0; k < 64; k += 4) {
        ulonglong2 a[4];
        a[0] = *(const ulonglong2*)(ap + k);
        a[1] = *(const ulonglong2*)(ap + 16*68 + k);
        a[2] = *(const ulonglong2*)(ap + 32*68 + k);
        a[3] = *(const ulonglong2*)(ap + 48*68 + k);
        #pragma unroll
        for (int j = 0; j < 8; j++) {
            ulonglong2 b = *(const ulonglong2*)(wp + j*8*68 + k);
            #pragma unroll
            for (int i = 0; i < 4; i++) {
                FMA2(acc[i][j], a[i].x, b.x);
                FMA2(acc[i][j], a[i].y, b.y);
            }
        }
    }
    #pragma unroll
    for (int j = 0; j < 8; j++) {
        int jj = j0 + 8*j;
        float bj = __ldg(bias + jj);
        #pragma unroll
        for (int i = 0; i < 4; i++) {
            int row = r + 16*i;
            float lo, hi; UNPK(lo, hi, acc[i][j]);
            og[jj*64 + row] = lo + hi + bj;
        }
    }
}

// splat a 10-float window into 8+2 packed pairs
#define SPLAT10(XR, sp) { \
    float4 v0 = *(const float4*)(XR); \
    float4 v1 = *(const float4*)((XR)+4); \
    float2 v2 = *(const float2*)((XR)+8); \
    PK(sp[0],v0.x,v0.x); PK(sp[1],v0.y,v0.y); PK(sp[2],v0.z,v0.z); PK(sp[3],v0.w,v0.w); \
    PK(sp[4],v1.x,v1.x); PK(sp[5],v1.y,v1.y); PK(sp[6],v1.z,v1.z); PK(sp[7],v1.w,v1.w); \
    PK(sp[8],v2.x,v2.x); PK(sp[9],v2.y,v2.y); }

// conv channel-pair step: weights come pre-paired (o2,o2+8) -> direct u64 operands
#define CONV_PAIR(XR0, XR1, WT) { \
    ulonglong2 L0 = __ldg((const ulonglong2*)(WT)); \
    ulonglong2 L1 = __ldg((const ulonglong2*)((WT)+4)); \
    ulonglong2 L2 = __ldg((const ulonglong2*)((WT)+8)); \
    u64 sp[10]; \
    SPLAT10(XR0, sp); \
    _Pragma("unroll") \
    for (int ii = 0; ii < 8; ii++) { \
        FMA2(a[ii], L0.x, sp[ii]); FMA2(a[ii], L0.y, sp[ii+1]); FMA2(a[ii], L1.x, sp[ii+2]); } \
    SPLAT10(XR1, sp); \
    _Pragma("unroll") \
    for (int ii = 0; ii < 8; ii++) { \
        FMA2(a[ii], L1.y, sp[ii]); FMA2(a[ii], L2.x, sp[ii+1]); FMA2(a[ii], L2.y, sp[ii+2]); } }

// gemm phase: compute warps run GEMM, prefetch warps stage next weights
#define GPHASE(RELU, BM, IN, SIN, WCUR, BIAS, OUT, SO, NXT, WNXT) { \
    if (tid < 128) gemm48<RELU, BM>(IN, SIN, WCUR, BIAS, OUT, SO, tid); \
    else stage_w_half(NXT, WNXT, tid - 128); \
    __syncthreads(); }

// ---------------- main fused kernel: one CTA per batch element ----------------
// smem (floats): X 0(4352) | CB 4352(4352) | T 8704(4352) | PF 13056(4352)
//                | W0 17408(4352) | W1 21760(4352; aliased as 4x Y1 during conv)
//                | LNS 26112(128)
#define SMEM_FLOATS 26240

__global__ void __launch_bounds__(NT, 2)
esa_main_kernel(const float* __restrict__ x,
                const float* __restrict__ conv1_b, const float* __restrict__ conv2_b,
                const float* __restrict__ pm1_w,
                const float* __restrict__ pm2_w, const float* __restrict__ pm2_b,
                const float* __restrict__ mo_w,  const float* __restrict__ mo_b,
                const float* __restrict__ out_w, const float* __restrict__ out_b,
                const float* __restrict__ ln_g,  const float* __restrict__ ln_b,
                float* __restrict__ out)
{
    extern __shared__ float sm[];
    const int tid = threadIdx.x;
    const int b = blockIdx.x;
    float* X   = sm;
    float* CB  = sm + 4352;
    float* T   = sm + 8704;
    float* PF  = sm + 13056;
    float* W0  = sm + 17408;
    float* W1  = sm + 21760;
    float* LNS = sm + 26112;

    // ---- load x + stage pm1 into W0 + stage ln_g/ln_b ----
    {
        float4 pw[4]; pre_ld(pm1_w, 80, pw, tid);
        const float* xg = x + (size_t)b * 4096;
        for (int idx4 = tid; idx4 < 1024; idx4 += NT) {
            float4 v = __ldg((const float4*)xg + idx4);
            int c = idx4 >> 4, n = (idx4 & 15) << 2;
            float* rr = X + c*68 + 1 + n;
            rr[0] = v.x; rr[1] = v.y; rr[2] = v.z; rr[3] = v.w;
        }
        pre_st(W0, pw, tid);
        if (tid < 64) {
            X[tid*68] = 0.f;  X[tid*68 + 65] = 0.f;    // x pads
            W1[tid*68] = 0.f; W1[tid*68 + 65] = 0.f;   // Y1 pads (4 scales x 16 rows)
            LNS[tid]      = __ldg(ln_g + tid);
            LNS[64 + tid] = __ldg(ln_b + tid);
        }
    }
    __syncthreads();

    // ---- conv stack: 4 scales in one pass; thread = (s, o2, nq), 2 out-ch each ----
    {
        const int s  = tid >> 6;
        const int o2 = (tid >> 3) & 7;
        const int nq = tid & 7;
        const int base = nq * 8;
        float* Y1 = W1 + s*1088;
        {   // conv1: 64 -> 16 channels (channel pairs)
            const float* wt = g_cw1p + ((s*32)*8 + o2)*16;
            u64 a[8];
            #pragma unroll
            for (int j = 0; j < 8; j++) a[j] = 0ull;
            #pragma unroll 2
            for (int c2 = 0; c2 < 32; c2++)
                CONV_PAIR(X + (2*c2)*68 + base, X + (2*c2+1)*68 + base, wt + c2*128);
            float bb0 = __ldg(conv1_b + s*16 + o2);
            float bb1 = __ldg(conv1_b + s*16 + o2 + 8);
            float* y0 = Y1 + o2*68 + 1 + base;
            float* y1r = Y1 + (o2+8)*68 + 1 + base;
            #pragma unroll
            for (int j = 0; j < 8; j++) {
                float lo, hi; UNPK(lo, hi, a[j]);
                y0[j]  = fmaxf(lo+bb0, 0.f);
                y1r[j] = fmaxf(hi+bb1, 0.f);
            }
        }
        __syncthreads();
        {   // conv2: 16 -> 16 channels, swizzled transposed store into CB
            const float* wt = g_cw2p + ((s*8)*8 + o2)*16;
            u64 a[8];
            #pragma unroll
            for (int j = 0; j < 8; j++) a[j] = 0ull;
            #pragma unroll
            for (int c2 = 0; c2 < 8; c2++)
                CONV_PAIR(Y1 + (2*c2)*68 + base, Y1 + (2*c2+1)*68 + base, wt + c2*128);
            float bb0 = __ldg(conv2_b + s*16 + o2);
            float bb1 = __ldg(conv2_b + s*16 + o2 + 8);
            float olo[8], ohi[8];
            #pragma unroll
            for (int j = 0; j < 8; j++) UNPK(olo[j], ohi[j], a[j]);
            int ch0 = s*16 + o2, ch1 = ch0 + 8;
            #pragma unroll
            for (int ii = 0; ii < 8; ii++) {
                int rr = (ii + nq) & 7;     // bank-conflict-free rotation
                CB[(base+rr)*68 + ch0] = fmaxf(olo[rr]+bb0, 0.f);
                CB[(base+rr)*68 + ch1] = fmaxf(ohi[rr]+bb1, 0.f);
            }
        }
        __syncthreads();
    }

    // ---- GEMM chain: compute warps (0-3) + prefetch warps (4-7) ----
    GPHASE(true,  true,  CB, 68, W0, g_p16,  T,  68, pm2_w, W1);  // pm1
    GPHASE(false, false, T,  68, W1, pm2_b,  PF, 68, g_wq,  W0);  // pm2
    GPHASE(false, false, PF, 68, W0, g_bq,   CB, 68, g_wk,  W1);  // Q
    GPHASE(false, false, PF, 68, W1, g_bk,   T,  68, g_wv,  W0);  // K
    GPHASE(false, false, PF, 68, W0, g_bv,   X,  68, mo_w,  W1);  // V

    // ---- attention: single pass, no max-sub (scores are small), 2 rows/lane ----
    {
        const int h8 = (tid >> 5) * 8;
        const int n0 = tid & 31;
        const float* q0p = CB + n0*68 + h8;
        const float* q1p = q0p + 32*68;
        ulonglong2 qa0 = *(const ulonglong2*)q0p;
        ulonglong2 qb0 = *(const ulonglong2*)(q0p + 4);
        ulonglong2 qa1 = *(const ulonglong2*)q1p;
        ulonglong2 qb1 = *(const ulonglong2*)(q1p + 4);
        float su0 = 0.f, su1 = 0.f;
        u64 c0[4] = {0ull,0ull,0ull,0ull};
        u64 c1[4] = {0ull,0ull,0ull,0ull};
        #pragma unroll 4
        for (int m = 0; m < 64; m++) {
            const float* kr = T + m*68 + h8;
            const float* vr = X + m*68 + h8;
            ulonglong2 ka = *(const ulonglong2*)kr;
            ulonglong2 kb = *(const ulonglong2*)(kr + 4);
            ulonglong2 va = *(const ulonglong2*)vr;
            ulonglong2 vb = *(const ulonglong2*)(vr + 4);
            u64 d0 = 0ull, d1 = 0ull;
            FMA2(d0, qa0.x, ka.x); FMA2(d0, qa0.y, ka.y);
            FMA2(d0, qb0.x, kb.x); FMA2(d0, qb0.y, kb.y);
            FMA2(d1, qa1.x, ka.x); FMA2(d1, qa1.y, ka.y);
            FMA2(d1, qb1.x, kb.x); FMA2(d1, qb1.y, kb.y);
            float lo, hi;
            UNPK(lo, hi, d0); float e0 = __expf(lo + hi);
            UNPK(lo, hi, d1); float e1 = __expf(lo + hi);
            su0 += e0; su1 += e1;
            u64 e0p, e1p;
            PK(e0p, e0, e0); PK(e1p, e1, e1);
            FMA2(c0[0], e0p, va.x); FMA2(c0[1], e0p, va.y);
            FMA2(c0[2], e0p, vb.x); FMA2(c0[3], e0p, vb.y);
            FMA2(c1[0], e1p, va.x); FMA2(c1[1], e1p, va.y);
            FMA2(c1[2], e1p, vb.x); FMA2(c1[3], e1p, vb.y);
        }
        float inv0 = 1.f / su0, inv1 = 1.f / su1;
        float w0l,w0h,w1l,w1h,w2l,w2h,w3l,w3h;
        UNPK(w0l,w0h,c0[0]); UNPK(w1l,w1h,c0[1]); UNPK(w2l,w2h,c0[2]); UNPK(w3l,w3h,c0[3]);
        *(float4*)(CB + n0*68 + h8)     = make_float4(w0l*inv0, w0h*inv0, w1l*inv0, w1h*inv0);
        *(float4*)(CB + n0*68 + h8 + 4) = make_float4(w2l*inv0, w2h*inv0, w3l*inv0, w3h*inv0);
        UNPK(w0l,w0h,c1[0]); UNPK(w1l,w1h,c1[1]); UNPK(w2l,w2h,c1[2]); UNPK(w3l,w3h,c1[3]);
        *(float4*)(CB + (n0+32)*68 + h8)     = make_float4(w0l*inv1, w0h*inv1, w1l*inv1, w1h*inv1);
        *(float4*)(CB + (n0+32)*68 + h8 + 4) = make_float4(w2l*inv1, w2h*inv1, w3l*inv1, w3h*inv1);
    }
    __syncthreads();

    // ---- mo + geo + residual + fused LayerNorm (warps 0-3); stage out_w (4-7) ----
    if (tid < 128) gemm_mo_ln48(CB, W1, mo_b, PF, LNS, T, tid);
    else stage_w_half(out_w, W0, tid - 128);
    __syncthreads();

    // ---- final projection: straight to global, transposed layout ----
    if (tid < 128) gemm_out48(T, W0, out_b, out + (size_t)b * 4096, tid);
}

// ---------------- launch ----------------
extern "C" void kernel_launch(void* const* d_in, const int* in_sizes, int n_in,
                              void* d_out, int out_size)
{
    const float* x         = (const float*)d_in[0];
    const float* points    = (const float*)d_in[1];
    const float* conv1_w   = (const float*)d_in[2];
    const float* conv1_b   = (const float*)d_in[3];
    const float* conv2_w   = (const float*)d_in[4];
    const float* conv2_b   = (const float*)d_in[5];
    const float* pattern   = (const float*)d_in[6];
    const float* pm1_w     = (const float*)d_in[7];
    const float* pm1_b     = (const float*)d_in[8];
    const float* pm2_w     = (const float*)d_in[9];
    const float* pm2_b     = (const float*)d_in[10];
    const float* q_w       = (const float*)d_in[11];
    const float* q_b       = (const float*)d_in[12];
    const float* k_w       = (const float*)d_in[13];
    const float* k_b       = (const float*)d_in[14];
    const float* v_w       = (const float*)d_in[15];
    const float* v_b       = (const float*)d_in[16];
    const float* in_w      = (const float*)d_in[17];
    const float* in_b      = (const float*)d_in[18];
    const float* mo_w      = (const float*)d_in[19];
    const float* mo_b      = (const float*)d_in[20];
    const float* out_w     = (const float*)d_in[21];
    const float* out_b     = (const float*)d_in[22];
    const float* ln_g      = (const float*)d_in[23];
    const float* ln_b      = (const float*)d_in[24];
    const int*   adjacency = (const int*)d_in[25];

    int B = in_sizes[0] / 4096;
    size_t smem = SMEM_FLOATS * sizeof(float);
    cudaFuncSetAttribute(esa_main_kernel, cudaFuncAttributeMaxDynamicSharedMemorySize, (int)smem);

    esa_prep_kernel<<<24, NT>>>(points, adjacency, in_w, in_b, pattern, pm1_w, pm1_b,
                                conv1_w, conv2_w,
                                q_w, q_b, k_w, k_b, v_w, v_b);
    esa_main_kernel<<<B, NT, smem>>>(x, conv1_b, conv2_b,
                                     pm1_w, pm2_w, pm2_b, mo_w, mo_b,
                                     out_w, out_b, ln_g, ln_b, (float*)d_out);
}